// round 13
// baseline (speedup 1.0000x reference)
#include <cuda_runtime.h>
#include <cuda_bf16.h>
#include <cstdint>
#include <stdint.h>
#include <math.h>

// ---------------------------------------------------------------------------
// GCN 3-layer. Round 12: GEMM1 = cp.async raw tiles -> convert-ONCE into
// packed bf16x2 hi/lo smem (double-buffered), MMAs of tile t overlap the
// conversion of tile t+1. Small GEMMs = R11 convert-on-read kernel with
// bank-conflict fix (SB=BN+4). CSR gather SpMM + fused spmm16+log_softmax.
// ---------------------------------------------------------------------------

#define NN 50000
#define EE 800000

__device__ float g_support[NN * 128];
__device__ float g_h1[NN * 128];
__device__ float g_h2[NN * 64];
__device__ int   g_counts[NN + 1];
__device__ int   g_offsets[NN + 1];
__device__ int   g_cursor[NN];
__device__ int   g_col[EE];
__device__ float g_val[EE];

__device__ __forceinline__ uint32_t smem_u32(const void* p) {
    uint32_t a;
    asm("{ .reg .u64 t; cvta.to.shared.u64 t, %1; cvt.u32.u64 %0, t; }" : "=r"(a) : "l"(p));
    return a;
}

// pack (x=k_even, y=k_odd) -> hi bf16x2 and lo (residual) bf16x2
__device__ __forceinline__ void packpair(float x, float y, uint32_t& h, uint32_t& l) {
    uint32_t p;
    asm("cvt.rn.bf16x2.f32 %0, %1, %2;" : "=r"(p) : "f"(y), "f"(x));
    float xr = __uint_as_float(p << 16);
    float yr = __uint_as_float(p & 0xffff0000u);
    uint32_t q;
    asm("cvt.rn.bf16x2.f32 %0, %1, %2;" : "=r"(q) : "f"(y - yr), "f"(x - xr));
    h = p; l = q;
}

#define MMA_BF16(c, a, b)                                                    \
    asm volatile(                                                            \
        "mma.sync.aligned.m16n8k16.row.col.f32.bf16.bf16.f32 "               \
        "{%0,%1,%2,%3}, {%4,%5,%6,%7}, {%8,%9}, {%0,%1,%2,%3};\n"            \
        : "+f"((c)[0]), "+f"((c)[1]), "+f"((c)[2]), "+f"((c)[3])             \
        : "r"((a)[0]), "r"((a)[1]), "r"((a)[2]), "r"((a)[3]),                \
          "r"((b)[0]), "r"((b)[1]))

#define CP_ASYNC16(dst, src, sz) \
    asm volatile("cp.async.cg.shared.global [%0], [%1], 16, %2;" \
                 :: "r"(dst), "l"(src), "r"(sz))
#define CP_COMMIT() asm volatile("cp.async.commit_group;" ::: "memory")

// ------------------------------ CSR build ----------------------------------

__global__ void hist_kernel(const int* __restrict__ src, int* __restrict__ counts, int E) {
    int i = blockIdx.x * blockDim.x + threadIdx.x;
    if (i < E) atomicAdd(&counts[src[i]], 1);
}

__global__ void scan_kernel(const int* __restrict__ counts, int* __restrict__ offsets, int n) {
    const int T = 1024;
    __shared__ int wsum[32];
    int tid = threadIdx.x;
    int per = (n + T - 1) / T;
    int beg = tid * per;
    int end = min(beg + per, n);
    int sum = 0;
    for (int i = beg; i < end; i++) sum += counts[i];
    int lane = tid & 31, wid = tid >> 5;
    int v = sum;
    #pragma unroll
    for (int off = 1; off < 32; off <<= 1) {
        int t2 = __shfl_up_sync(0xffffffffu, v, off);
        if (lane >= off) v += t2;
    }
    if (lane == 31) wsum[wid] = v;
    __syncthreads();
    if (wid == 0) {
        int w = wsum[lane];
        #pragma unroll
        for (int off = 1; off < 32; off <<= 1) {
            int t2 = __shfl_up_sync(0xffffffffu, w, off);
            if (lane >= off) w += t2;
        }
        wsum[lane] = w;
    }
    __syncthreads();
    int pre = v - sum + (wid > 0 ? wsum[wid - 1] : 0);
    int run = pre;
    for (int i = beg; i < end; i++) { offsets[i] = run; run += counts[i]; }
    if (end == n) offsets[n] = run;
}

__global__ void scatter_kernel(const int* __restrict__ src, const int* __restrict__ dst,
                               const float* __restrict__ ev,
                               const int* __restrict__ offsets, int* __restrict__ cursor,
                               int* __restrict__ col, float* __restrict__ val, int E) {
    int i = blockIdx.x * blockDim.x + threadIdx.x;
    if (i < E) {
        int s = src[i];
        int pos = offsets[s] + atomicAdd(&cursor[s], 1);
        col[pos] = dst[i];
        val[pos] = ev[i];
    }
}

// ------------------- GEMM1: packed-convert pipeline (512 thr) --------------
// C[M,128] = A[M,K] @ B[K,128]. BM=128, BN=128, BK=32.

static constexpr int G1_BM = 128, G1_BN = 128, G1_BK = 32, G1_NSTAGE = 3;
static constexpr int G1_BKP = G1_BK / 2;              // 16 k-pairs
static constexpr int G1_SAR = G1_BK + 4;              // raw A stride
static constexpr int G1_SBR = G1_BN + 4;              // raw B stride
static constexpr int G1_RAWST = G1_BM * G1_SAR + G1_BK * G1_SBR;
static constexpr int G1_SAP = G1_BKP + 4;             // 20: conflict-free frag reads
static constexpr int G1_SBP = G1_BN + 8;              // 136: tq*SBP = {0,8,16,24} banks
static constexpr int G1_PA = G1_BM * G1_SAP;          // 2560
static constexpr int G1_PB = G1_BKP * G1_SBP;         // 2176
static constexpr int G1_PKST = 2 * G1_PA + 2 * G1_PB; // per packed buffer (u32)
static constexpr int G1_SMEM = (G1_NSTAGE * G1_RAWST + 2 * G1_PKST) * 4;

__global__ void __launch_bounds__(512, 1)
gemm1_packed_kernel(int M, int K,
                    const float* __restrict__ A, const float* __restrict__ B,
                    float* __restrict__ C) {
    constexpr int THREADS = 512;
    constexpr int MT = 2, NT = 4;                 // 4x4 warps, WM=32, WN=32
    extern __shared__ float smemf[];
    uint32_t* pk = (uint32_t*)(smemf + G1_NSTAGE * G1_RAWST);

    const int tid = threadIdx.x;
    const int warp = tid >> 5, lane = tid & 31;
    const int wm = (warp >> 2) * 32;
    const int wn = (warp & 3) * 32;
    const int g = lane >> 2, tq = lane & 3;
    const int row0 = blockIdx.x * G1_BM;
    const int ntiles = (K + G1_BK - 1) / G1_BK;

    float acc[MT][NT][4];
    #pragma unroll
    for (int mi = 0; mi < MT; mi++)
        #pragma unroll
        for (int ni = 0; ni < NT; ni++)
            #pragma unroll
            for (int q = 0; q < 4; q++) acc[mi][ni][q] = 0.f;

    auto issue_tile = [&](int tile) {
        if (tile >= ntiles) return;
        int k0 = tile * G1_BK;
        float* as = smemf + (tile % G1_NSTAGE) * G1_RAWST;
        float* bs = as + G1_BM * G1_SAR;
        #pragma unroll
        for (int it = 0; it < (G1_BM * G1_BK / 4) / THREADS; it++) {
            int i = tid + it * THREADS;
            int r = i / (G1_BK / 4), q = i % (G1_BK / 4);
            int gm = row0 + r, gk = k0 + q * 4;
            uint32_t dst = smem_u32(as + r * G1_SAR + q * 4);
            const float* src = A + (long)gm * K + gk;
            int sz = (gm < M && gk < K) ? 16 : 0;
            CP_ASYNC16(dst, src, sz);
        }
        #pragma unroll
        for (int it = 0; it < (G1_BK * G1_BN / 4) / THREADS; it++) {
            int i = tid + it * THREADS;
            int r = i / (G1_BN / 4), q = i % (G1_BN / 4);
            int gk = k0 + r;
            uint32_t dst = smem_u32(bs + r * G1_SBR + q * 4);
            const float* src = B + (long)gk * G1_BN + q * 4;
            int sz = (gk < K) ? 16 : 0;
            CP_ASYNC16(dst, src, sz);
        }
    };

    auto convert_tile = [&](int tile) {
        if (tile >= ntiles) return;
        const float* as = smemf + (tile % G1_NSTAGE) * G1_RAWST;
        const float* bs = as + G1_BM * G1_SAR;
        uint32_t* aph = pk + (tile & 1) * G1_PKST;
        uint32_t* apl = aph + G1_PA;
        uint32_t* bph = apl + G1_PA;
        uint32_t* bpl = bph + G1_PB;
        #pragma unroll
        for (int it = 0; it < (G1_BM * G1_BKP) / THREADS; it++) {
            int i = tid + it * THREADS;
            int r = i / G1_BKP, p = i % G1_BKP;
            float2 v = *(const float2*)(as + r * G1_SAR + 2 * p);
            uint32_t h, l;
            packpair(v.x, v.y, h, l);
            aph[r * G1_SAP + p] = h;
            apl[r * G1_SAP + p] = l;
        }
        #pragma unroll
        for (int it = 0; it < (G1_BKP * G1_BN) / THREADS; it++) {
            int i = tid + it * THREADS;
            int p = i / G1_BN, c = i % G1_BN;
            float b0 = bs[(2 * p) * G1_SBR + c];
            float b1 = bs[(2 * p + 1) * G1_SBR + c];
            uint32_t h, l;
            packpair(b0, b1, h, l);
            bph[p * G1_SBP + c] = h;
            bpl[p * G1_SBP + c] = l;
        }
    };

    // prologue: tiles 0..NSTAGE-2 in flight; convert tile 0
    #pragma unroll
    for (int s = 0; s < G1_NSTAGE - 1; s++) { issue_tile(s); CP_COMMIT(); }
    asm volatile("cp.async.wait_group %0;" :: "n"(G1_NSTAGE - 2) : "memory");
    __syncthreads();
    convert_tile(0);
    __syncthreads();

    for (int t = 0; t < ntiles; t++) {
        issue_tile(t + G1_NSTAGE - 1);
        CP_COMMIT();
        asm volatile("cp.async.wait_group %0;" :: "n"(G1_NSTAGE - 2) : "memory");
        // raw tile t+1 landed; packed tile t ready.

        const uint32_t* aph = pk + (t & 1) * G1_PKST;
        const uint32_t* apl = aph + G1_PA;
        const uint32_t* bph = apl + G1_PA;
        const uint32_t* bpl = bph + G1_PB;

        // MMAs on packed[t] (tensor pipe) ...
        #pragma unroll
        for (int ks = 0; ks < G1_BKP / 8; ks++) {
            const int kp0 = ks * 8;
            uint32_t fah[MT][4], fal[MT][4], fbh[NT][2], fbl[NT][2];
            #pragma unroll
            for (int mi = 0; mi < MT; mi++) {
                int r = wm + mi * 16 + g;
                fah[mi][0] = aph[r * G1_SAP + kp0 + tq];
                fah[mi][1] = aph[(r + 8) * G1_SAP + kp0 + tq];
                fah[mi][2] = aph[r * G1_SAP + kp0 + tq + 4];
                fah[mi][3] = aph[(r + 8) * G1_SAP + kp0 + tq + 4];
                fal[mi][0] = apl[r * G1_SAP + kp0 + tq];
                fal[mi][1] = apl[(r + 8) * G1_SAP + kp0 + tq];
                fal[mi][2] = apl[r * G1_SAP + kp0 + tq + 4];
                fal[mi][3] = apl[(r + 8) * G1_SAP + kp0 + tq + 4];
            }
            #pragma unroll
            for (int ni = 0; ni < NT; ni++) {
                int c = wn + ni * 8 + g;
                fbh[ni][0] = bph[(kp0 + tq) * G1_SBP + c];
                fbh[ni][1] = bph[(kp0 + tq + 4) * G1_SBP + c];
                fbl[ni][0] = bpl[(kp0 + tq) * G1_SBP + c];
                fbl[ni][1] = bpl[(kp0 + tq + 4) * G1_SBP + c];
            }
            #pragma unroll
            for (int mi = 0; mi < MT; mi++)
                #pragma unroll
                for (int ni = 0; ni < NT; ni++) {
                    MMA_BF16(acc[mi][ni], fah[mi], fbh[ni]);
                    MMA_BF16(acc[mi][ni], fal[mi], fbh[ni]);
                    MMA_BF16(acc[mi][ni], fah[mi], fbl[ni]);
                }
        }

        // ... overlapped with conversion of raw[t+1] (alu/fma pipes)
        convert_tile(t + 1);
        __syncthreads();
    }

    // epilogue
    #pragma unroll
    for (int mi = 0; mi < MT; mi++) {
        int r = row0 + wm + mi * 16 + g;
        #pragma unroll
        for (int ni = 0; ni < NT; ni++) {
            int c = wn + ni * 8 + 2 * tq;
            if (r < M)
                *(float2*)(C + (long)r * G1_BN + c) = make_float2(acc[mi][ni][0], acc[mi][ni][1]);
            if (r + 8 < M)
                *(float2*)(C + (long)(r + 8) * G1_BN + c) = make_float2(acc[mi][ni][2], acc[mi][ni][3]);
        }
    }
}

// ------------------------------ bf16 GEMM (cp.async, convert-on-read) ------
// Used for the small GEMMs. SB = BN+4 (bank-conflict fix).

constexpr int gemm_smem_bytes(int BM, int BN, int BK, int NSTAGE) {
    int SA = BK + 4, SB = BN + 4;
    return NSTAGE * (BM * SA + BK * SB) * 4;
}

template <int BM, int BN, int BK, int WARPS_M, int WARPS_N, int NSTAGE, bool BIAS>
__global__ void __launch_bounds__(32 * WARPS_M * WARPS_N,
                                  (32 * WARPS_M * WARPS_N <= 256) ? 2 : 1)
bf16cp_gemm_kernel(int M, int N, int K,
                   const float* __restrict__ A, const float* __restrict__ B,
                   const float* __restrict__ bias, float* __restrict__ C) {
    constexpr int THREADS = 32 * WARPS_M * WARPS_N;
    constexpr int WM = BM / WARPS_M, WN = BN / WARPS_N;
    constexpr int MT = WM / 16, NT = WN / 8;
    constexpr int SA = BK + 4;
    constexpr int SB = BN + 4;
    constexpr int A_ST = BM * SA, B_ST = BK * SB;
    constexpr int AITEMS = BM * BK / 4;
    constexpr int BITEMS = BK * BN / 4;

    extern __shared__ float smemf[];

    const int tid = threadIdx.x;
    const int warp = tid >> 5, lane = tid & 31;
    const int wm = (warp / WARPS_N) * WM;
    const int wn = (warp % WARPS_N) * WN;
    const int g = lane >> 2, tq = lane & 3;
    const int row0 = blockIdx.y * BM;
    const int ntiles = (K + BK - 1) / BK;

    float acc[MT][NT][4];
    #pragma unroll
    for (int mi = 0; mi < MT; mi++)
        #pragma unroll
        for (int ni = 0; ni < NT; ni++)
            #pragma unroll
            for (int q = 0; q < 4; q++) acc[mi][ni][q] = 0.f;

    auto issue_tile = [&](int tile) {
        if (tile >= ntiles) return;
        int k0 = tile * BK;
        float* as = smemf + (tile % NSTAGE) * (A_ST + B_ST);
        float* bs = as + A_ST;
        #pragma unroll
        for (int i = tid; i < AITEMS; i += THREADS) {
            int r = i / (BK / 4), q = i % (BK / 4);
            int gm = row0 + r, gk = k0 + q * 4;
            uint32_t dst = smem_u32(as + r * SA + q * 4);
            const float* src = A + (long)gm * K + gk;
            int sz = (gm < M && gk < K) ? 16 : 0;
            CP_ASYNC16(dst, src, sz);
        }
        #pragma unroll
        for (int i = tid; i < BITEMS; i += THREADS) {
            int r = i / (BN / 4), q = i % (BN / 4);
            int gk = k0 + r;
            uint32_t dst = smem_u32(bs + r * SB + q * 4);
            const float* src = B + (long)gk * N + q * 4;
            int sz = (gk < K) ? 16 : 0;
            CP_ASYNC16(dst, src, sz);
        }
    };

    #pragma unroll
    for (int s = 0; s < NSTAGE - 1; s++) { issue_tile(s); CP_COMMIT(); }

    for (int t = 0; t < ntiles; t++) {
        asm volatile("cp.async.wait_group %0;" :: "n"(NSTAGE - 2) : "memory");
        __syncthreads();
        issue_tile(t + NSTAGE - 1);
        CP_COMMIT();

        const float* as = smemf + (t % NSTAGE) * (A_ST + B_ST);
        const float* bs = as + A_ST;

        #pragma unroll
        for (int kk = 0; kk < BK; kk += 16) {
            uint32_t fah[MT][4], fal[MT][4], fbh[NT][2], fbl[NT][2];
            #pragma unroll
            for (int mi = 0; mi < MT; mi++) {
                int r = wm + mi * 16 + g;
                float2 a0 = *(const float2*)(as + r * SA + kk + 2 * tq);
                float2 a1 = *(const float2*)(as + (r + 8) * SA + kk + 2 * tq);
                float2 a2 = *(const float2*)(as + r * SA + kk + 2 * tq + 8);
                float2 a3 = *(const float2*)(as + (r + 8) * SA + kk + 2 * tq + 8);
                packpair(a0.x, a0.y, fah[mi][0], fal[mi][0]);
                packpair(a1.x, a1.y, fah[mi][1], fal[mi][1]);
                packpair(a2.x, a2.y, fah[mi][2], fal[mi][2]);
                packpair(a3.x, a3.y, fah[mi][3], fal[mi][3]);
            }
            #pragma unroll
            for (int ni = 0; ni < NT; ni++) {
                int c = wn + ni * 8 + g;
                float b00 = bs[(kk + 2 * tq) * SB + c];
                float b01 = bs[(kk + 2 * tq + 1) * SB + c];
                float b10 = bs[(kk + 2 * tq + 8) * SB + c];
                float b11 = bs[(kk + 2 * tq + 9) * SB + c];
                packpair(b00, b01, fbh[ni][0], fbl[ni][0]);
                packpair(b10, b11, fbh[ni][1], fbl[ni][1]);
            }
            #pragma unroll
            for (int mi = 0; mi < MT; mi++)
                #pragma unroll
                for (int ni = 0; ni < NT; ni++) {
                    MMA_BF16(acc[mi][ni], fah[mi], fbh[ni]);
                    MMA_BF16(acc[mi][ni], fal[mi], fbh[ni]);
                    MMA_BF16(acc[mi][ni], fah[mi], fbl[ni]);
                }
        }
    }

    #pragma unroll
    for (int mi = 0; mi < MT; mi++) {
        int r = row0 + wm + mi * 16 + g;
        #pragma unroll
        for (int ni = 0; ni < NT; ni++) {
            int c = wn + ni * 8 + 2 * tq;
            float bx = 0.f, by = 0.f;
            if (BIAS) { bx = bias[c]; by = bias[c + 1]; }
            if (r < M)
                *(float2*)(C + (long)r * N + c) = make_float2(acc[mi][ni][0] + bx, acc[mi][ni][1] + by);
            if (r + 8 < M)
                *(float2*)(C + (long)(r + 8) * N + c) = make_float2(acc[mi][ni][2] + bx, acc[mi][ni][3] + by);
        }
    }
}

// ------------------------------ CSR SpMM -----------------------------------

template <bool RELU>
__global__ void spmm128_kernel(const float* __restrict__ support,
                               const int* __restrict__ offsets,
                               const int* __restrict__ col,
                               const float* __restrict__ val,
                               const float* __restrict__ bias,
                               float* __restrict__ out, int n) {
    int warp = (blockIdx.x * blockDim.x + threadIdx.x) >> 5;
    int lane = threadIdx.x & 31;
    if (warp >= n) return;
    int start = offsets[warp], end = offsets[warp + 1];
    const float4* sup4 = (const float4*)support;
    float4 acc = make_float4(0.f, 0.f, 0.f, 0.f);
    int j = start;
    for (; j + 2 <= end; j += 2) {
        int c0 = col[j], c1 = col[j + 1];
        float w0 = val[j], w1 = val[j + 1];
        float4 s0 = sup4[c0 * 32 + lane];
        float4 s1 = sup4[c1 * 32 + lane];
        acc.x += w0 * s0.x + w1 * s1.x;
        acc.y += w0 * s0.y + w1 * s1.y;
        acc.z += w0 * s0.z + w1 * s1.z;
        acc.w += w0 * s0.w + w1 * s1.w;
    }
    if (j < end) {
        int c = col[j]; float w = val[j];
        float4 s = sup4[c * 32 + lane];
        acc.x += w * s.x; acc.y += w * s.y; acc.z += w * s.z; acc.w += w * s.w;
    }
    float4 bb = ((const float4*)bias)[lane];
    acc.x += bb.x; acc.y += bb.y; acc.z += bb.z; acc.w += bb.w;
    if (RELU) {
        acc.x = fmaxf(acc.x, 0.f); acc.y = fmaxf(acc.y, 0.f);
        acc.z = fmaxf(acc.z, 0.f); acc.w = fmaxf(acc.w, 0.f);
    }
    ((float4*)out)[warp * 32 + lane] = acc;
}

template <bool RELU>
__global__ void spmm64_kernel(const float* __restrict__ support,
                              const int* __restrict__ offsets,
                              const int* __restrict__ col,
                              const float* __restrict__ val,
                              const float* __restrict__ bias,
                              float* __restrict__ out, int n) {
    int warp = (blockIdx.x * blockDim.x + threadIdx.x) >> 5;
    int lane = threadIdx.x & 31;
    if (warp >= n) return;
    int start = offsets[warp], end = offsets[warp + 1];
    const float2* sup2 = (const float2*)support;
    float2 acc = make_float2(0.f, 0.f);
    int j = start;
    for (; j + 2 <= end; j += 2) {
        int c0 = col[j], c1 = col[j + 1];
        float w0 = val[j], w1 = val[j + 1];
        float2 s0 = sup2[c0 * 32 + lane];
        float2 s1 = sup2[c1 * 32 + lane];
        acc.x += w0 * s0.x + w1 * s1.x;
        acc.y += w0 * s0.y + w1 * s1.y;
    }
    if (j < end) {
        int c = col[j]; float w = val[j];
        float2 s = sup2[c * 32 + lane];
        acc.x += w * s.x; acc.y += w * s.y;
    }
    float2 bb = ((const float2*)bias)[lane];
    acc.x += bb.x; acc.y += bb.y;
    if (RELU) { acc.x = fmaxf(acc.x, 0.f); acc.y = fmaxf(acc.y, 0.f); }
    ((float2*)out)[warp * 32 + lane] = acc;
}

__global__ void spmm16_lsm_kernel(const float* __restrict__ support,
                                  const int* __restrict__ offsets,
                                  const int* __restrict__ col,
                                  const float* __restrict__ val,
                                  const float* __restrict__ bias,
                                  float* __restrict__ out, int n) {
    int t = blockIdx.x * blockDim.x + threadIdx.x;
    int grp = t >> 4;
    int sub = t & 15;
    bool active = grp < n;
    int g2 = active ? grp : (n - 1);
    int start = offsets[g2], end = offsets[g2 + 1];
    float acc = 0.f;
    for (int j = start; j < end; j++)
        acc += val[j] * support[col[j] * 16 + sub];
    acc += bias[sub];
    float m = acc;
    #pragma unroll
    for (int off = 8; off >= 1; off >>= 1)
        m = fmaxf(m, __shfl_xor_sync(0xffffffffu, m, off, 16));
    float s = expf(acc - m);
    #pragma unroll
    for (int off = 8; off >= 1; off >>= 1)
        s += __shfl_xor_sync(0xffffffffu, s, off, 16);
    if (active) out[grp * 16 + sub] = acc - (logf(s) + m);
}

// ------------------------------ launch -------------------------------------

extern "C" void kernel_launch(void* const* d_in, const int* in_sizes, int n_in,
                              void* d_out, int out_size) {
    const float* x  = (const float*)d_in[0];
    const float* ev = (const float*)d_in[1];
    const float* W1 = (const float*)d_in[2];
    const float* b1 = (const float*)d_in[3];
    const float* W2 = (const float*)d_in[4];
    const float* b2 = (const float*)d_in[5];
    const float* W3 = (const float*)d_in[6];
    const float* b3 = (const float*)d_in[7];
    const float* We = (const float*)d_in[8];
    const float* be = (const float*)d_in[9];
    const int* esrc = (const int*)d_in[10];
    const int* edst = (const int*)d_in[11];

    const int N = NN;
    const int E = in_sizes[10];

    float* out1 = (float*)d_out;
    float* out2 = (float*)d_out + (long)N * 16;

    float *p_support, *p_h1, *p_h2, *p_val;
    int *p_counts, *p_offsets, *p_cursor, *p_col;
    cudaGetSymbolAddress((void**)&p_support, g_support);
    cudaGetSymbolAddress((void**)&p_h1, g_h1);
    cudaGetSymbolAddress((void**)&p_h2, g_h2);
    cudaGetSymbolAddress((void**)&p_counts, g_counts);
    cudaGetSymbolAddress((void**)&p_offsets, g_offsets);
    cudaGetSymbolAddress((void**)&p_cursor, g_cursor);
    cudaGetSymbolAddress((void**)&p_col, g_col);
    cudaGetSymbolAddress((void**)&p_val, g_val);

    constexpr int S2 = gemm_smem_bytes(128, 64, 32, 3);
    constexpr int S3 = gemm_smem_bytes(128, 16, 32, 3);
    cudaFuncSetAttribute(gemm1_packed_kernel,
                         cudaFuncAttributeMaxDynamicSharedMemorySize, G1_SMEM);
    cudaFuncSetAttribute(bf16cp_gemm_kernel<128, 64, 32, 4, 2, 3, false>,
                         cudaFuncAttributeMaxDynamicSharedMemorySize, S2);
    cudaFuncSetAttribute(bf16cp_gemm_kernel<128, 64, 32, 4, 2, 3, true>,
                         cudaFuncAttributeMaxDynamicSharedMemorySize, S2);
    cudaFuncSetAttribute(bf16cp_gemm_kernel<128, 16, 32, 8, 1, 3, false>,
                         cudaFuncAttributeMaxDynamicSharedMemorySize, S3);

    // ---- CSR build ----
    cudaMemsetAsync(p_counts, 0, (N + 1) * sizeof(int), 0);
    cudaMemsetAsync(p_cursor, 0, N * sizeof(int), 0);
    hist_kernel<<<(E + 255) / 256, 256>>>(esrc, p_counts, E);
    scan_kernel<<<1, 1024>>>(p_counts, p_offsets, N);
    scatter_kernel<<<(E + 255) / 256, 256>>>(esrc, edst, ev, p_offsets, p_cursor, p_col, p_val, E);

    // ---- layer 1: support = x@W1 [N,128]; h1 = relu(agg + b1) ----
    gemm1_packed_kernel<<<(N + 127) / 128, 512, G1_SMEM>>>(N, 500, x, W1, p_support);
    spmm128_kernel<true><<<(N * 32 + 255) / 256, 256>>>(p_support, p_offsets, p_col, p_val, b1, p_h1, N);

    dim3 grid(1, (N + 127) / 128);

    // ---- layer 2: support = h1@W2 [N,64]; h2 = relu(agg + b2) ----
    bf16cp_gemm_kernel<128, 64, 32, 4, 2, 3, false><<<grid, 256, S2>>>(N, 64, 128, p_h1, W2, nullptr, p_support);
    spmm64_kernel<true><<<(N * 32 + 255) / 256, 256>>>(p_support, p_offsets, p_col, p_val, b2, p_h2, N);

    // ---- layer 3: support = h2@W3 [N,16]; out1 = log_softmax(agg + b3) ----
    bf16cp_gemm_kernel<128, 16, 32, 8, 1, 3, false><<<grid, 256, S3>>>(N, 16, 64, p_h2, W3, nullptr, p_support);
    spmm16_lsm_kernel<<<(N * 16 + 255) / 256, 256>>>(p_support, p_offsets, p_col, p_val, b3, out1, N);

    // ---- head 2: out2 = h2@We + be ----
    bf16cp_gemm_kernel<128, 64, 32, 4, 2, 3, true><<<grid, 256, S2>>>(N, 64, 64, p_h2, We, be, out2);
}

// round 14
// speedup vs baseline: 1.0218x; 1.0218x over previous
#include <cuda_runtime.h>
#include <cuda_bf16.h>
#include <cstdint>
#include <stdint.h>
#include <math.h>

// ---------------------------------------------------------------------------
// GCN 3-layer. Round 13: bf16 hi/lo split moved OFF the GEMM critical path.
//  * Weights pre-split once into packed bf16x2 hi/lo globals.
//  * SpMM epilogues emit packed hi/lo h1/h2 (same bytes as fp32).
//  * Small GEMMs: pure cp.async of packed data -> frags -> MMA (no cvt at
//    all), 2-stage smem, 2 CTAs/SM.
//  * GEMM1: R12 overlap pipeline, converts A only (B lands packed).
// ---------------------------------------------------------------------------

#define NN 50000
#define EE 800000

__device__ float g_support[NN * 128];
__device__ uint32_t g_h1h[NN * 64];
__device__ uint32_t g_h1l[NN * 64];
__device__ uint32_t g_h2h[NN * 32];
__device__ uint32_t g_h2l[NN * 32];
__device__ int   g_counts[NN + 1];
__device__ int   g_offsets[NN + 1];
__device__ int   g_cursor[NN];
__device__ int   g_col[EE];
__device__ float g_val[EE];
// packed weights: [K/2 (padded)][N] bf16x2 hi/lo
__device__ uint32_t g_w1h[256 * 128], g_w1l[256 * 128];   // K=500->512
__device__ uint32_t g_w2h[64 * 64],  g_w2l[64 * 64];      // K=128
__device__ uint32_t g_w3h[32 * 16],  g_w3l[32 * 16];      // K=64
__device__ uint32_t g_weh[32 * 64],  g_wel[32 * 64];      // K=64

__device__ __forceinline__ uint32_t smem_u32(const void* p) {
    uint32_t a;
    asm("{ .reg .u64 t; cvta.to.shared.u64 t, %1; cvt.u32.u64 %0, t; }" : "=r"(a) : "l"(p));
    return a;
}

// pack (x=k_even, y=k_odd) -> hi bf16x2 and lo (residual) bf16x2
__device__ __forceinline__ void packpair(float x, float y, uint32_t& h, uint32_t& l) {
    uint32_t p;
    asm("cvt.rn.bf16x2.f32 %0, %1, %2;" : "=r"(p) : "f"(y), "f"(x));
    float xr = __uint_as_float(p << 16);
    float yr = __uint_as_float(p & 0xffff0000u);
    uint32_t q;
    asm("cvt.rn.bf16x2.f32 %0, %1, %2;" : "=r"(q) : "f"(y - yr), "f"(x - xr));
    h = p; l = q;
}

#define MMA_BF16(c, a, b)                                                    \
    asm volatile(                                                            \
        "mma.sync.aligned.m16n8k16.row.col.f32.bf16.bf16.f32 "               \
        "{%0,%1,%2,%3}, {%4,%5,%6,%7}, {%8,%9}, {%0,%1,%2,%3};\n"            \
        : "+f"((c)[0]), "+f"((c)[1]), "+f"((c)[2]), "+f"((c)[3])             \
        : "r"((a)[0]), "r"((a)[1]), "r"((a)[2]), "r"((a)[3]),                \
          "r"((b)[0]), "r"((b)[1]))

#define CP_ASYNC16(dst, src, sz) \
    asm volatile("cp.async.cg.shared.global [%0], [%1], 16, %2;" \
                 :: "r"(dst), "l"(src), "r"(sz))
#define CP_COMMIT() asm volatile("cp.async.commit_group;" ::: "memory")

// ------------------------------ weight split -------------------------------

__global__ void weight_split_kernel(const float* __restrict__ W,
                                    uint32_t* __restrict__ Wh, uint32_t* __restrict__ Wl,
                                    int K, int N, int KPtot) {
    int i = blockIdx.x * blockDim.x + threadIdx.x;
    if (i >= KPtot * N) return;
    int p = i / N, n = i % N;
    int k0 = 2 * p;
    float v0 = (k0 < K) ? W[(long)k0 * N + n] : 0.f;
    float v1 = (k0 + 1 < K) ? W[(long)(k0 + 1) * N + n] : 0.f;
    uint32_t h, l;
    packpair(v0, v1, h, l);
    Wh[i] = h; Wl[i] = l;
}

// ------------------------------ CSR build ----------------------------------

__global__ void hist_kernel(const int* __restrict__ src, int* __restrict__ counts, int E) {
    int i = blockIdx.x * blockDim.x + threadIdx.x;
    if (i < E) atomicAdd(&counts[src[i]], 1);
}

__global__ void scan_kernel(const int* __restrict__ counts, int* __restrict__ offsets, int n) {
    const int T = 1024;
    __shared__ int wsum[32];
    int tid = threadIdx.x;
    int per = (n + T - 1) / T;
    int beg = tid * per;
    int end = min(beg + per, n);
    int sum = 0;
    for (int i = beg; i < end; i++) sum += counts[i];
    int lane = tid & 31, wid = tid >> 5;
    int v = sum;
    #pragma unroll
    for (int off = 1; off < 32; off <<= 1) {
        int t2 = __shfl_up_sync(0xffffffffu, v, off);
        if (lane >= off) v += t2;
    }
    if (lane == 31) wsum[wid] = v;
    __syncthreads();
    if (wid == 0) {
        int w = wsum[lane];
        #pragma unroll
        for (int off = 1; off < 32; off <<= 1) {
            int t2 = __shfl_up_sync(0xffffffffu, w, off);
            if (lane >= off) w += t2;
        }
        wsum[lane] = w;
    }
    __syncthreads();
    int pre = v - sum + (wid > 0 ? wsum[wid - 1] : 0);
    int run = pre;
    for (int i = beg; i < end; i++) { offsets[i] = run; run += counts[i]; }
    if (end == n) offsets[n] = run;
}

__global__ void scatter_kernel(const int* __restrict__ src, const int* __restrict__ dst,
                               const float* __restrict__ ev,
                               const int* __restrict__ offsets, int* __restrict__ cursor,
                               int* __restrict__ col, float* __restrict__ val, int E) {
    int i = blockIdx.x * blockDim.x + threadIdx.x;
    if (i < E) {
        int s = src[i];
        int pos = offsets[s] + atomicAdd(&cursor[s], 1);
        col[pos] = dst[i];
        val[pos] = ev[i];
    }
}

// ------------------- GEMM1: A-convert pipeline (512 thr) -------------------
// C[M,128] = A[M,K] @ W1[K,128]; A fp32, W1 pre-packed (g_w1h/g_w1l).

static constexpr int G1_BM = 128, G1_BN = 128, G1_BK = 32;
static constexpr int G1_BKP = 16;
static constexpr int G1_SAR = G1_BK + 4;              // raw A stride (f32)
static constexpr int G1_RAW1 = G1_BM * G1_SAR;        // 4608 floats/stage
static constexpr int G1_SAP = G1_BKP + 4;             // 20
static constexpr int G1_SBP = G1_BN + 8;              // 136
static constexpr int G1_PA = G1_BM * G1_SAP;          // 2560 u32
static constexpr int G1_PB = G1_BKP * G1_SBP;         // 2176 u32
static constexpr int G1_SMEM = (3 * G1_RAW1 + 3 * 2 * G1_PB + 2 * 2 * G1_PA) * 4; // ~148.5KB

__global__ void __launch_bounds__(512, 1)
gemm1_packed_kernel(int M, int K,
                    const float* __restrict__ A,
                    const uint32_t* __restrict__ Bh, const uint32_t* __restrict__ Bl,
                    float* __restrict__ C) {
    constexpr int THREADS = 512;
    constexpr int MT = 2, NT = 4;
    extern __shared__ float smemf[];
    uint32_t* pk = (uint32_t*)(smemf + 3 * G1_RAW1);
    // B stages: pk + s*(2*G1_PB); packed A: pa + b*(2*G1_PA)
    uint32_t* pa = pk + 3 * 2 * G1_PB;

    const int tid = threadIdx.x;
    const int warp = tid >> 5, lane = tid & 31;
    const int wm = (warp >> 2) * 32;
    const int wn = (warp & 3) * 32;
    const int g = lane >> 2, tq = lane & 3;
    const int row0 = blockIdx.x * G1_BM;
    const int ntiles = (K + G1_BK - 1) / G1_BK;

    float acc[MT][NT][4];
    #pragma unroll
    for (int mi = 0; mi < MT; mi++)
        #pragma unroll
        for (int ni = 0; ni < NT; ni++)
            #pragma unroll
            for (int q = 0; q < 4; q++) acc[mi][ni][q] = 0.f;

    auto issue_tile = [&](int tile) {
        if (tile >= ntiles) return;
        int k0 = tile * G1_BK;
        float* as = smemf + (tile % 3) * G1_RAW1;
        uint32_t* bsh = pk + (tile % 3) * (2 * G1_PB);
        uint32_t* bsl = bsh + G1_PB;
        #pragma unroll
        for (int it = 0; it < 2; it++) {        // 1024 A chunks
            int i = tid + it * THREADS;
            int r = i >> 3, q = i & 7;
            int gm = row0 + r, gk = k0 + q * 4;
            uint32_t dst = smem_u32(as + r * G1_SAR + q * 4);
            const float* src = A + (long)gm * K + gk;
            int sz = (gm < M && gk < K) ? 16 : 0;
            CP_ASYNC16(dst, src, sz);
        }
        {                                        // 512 Bh chunks
            int i = tid;
            int p = i >> 5, q = i & 31;
            uint32_t dst = smem_u32(bsh + p * G1_SBP + q * 4);
            const uint32_t* src = Bh + (long)(tile * G1_BKP + p) * G1_BN + q * 4;
            CP_ASYNC16(dst, src, 16);
        }
        {                                        // 512 Bl chunks
            int i = tid;
            int p = i >> 5, q = i & 31;
            uint32_t dst = smem_u32(bsl + p * G1_SBP + q * 4);
            const uint32_t* src = Bl + (long)(tile * G1_BKP + p) * G1_BN + q * 4;
            CP_ASYNC16(dst, src, 16);
        }
    };

    auto convertA = [&](int tile) {
        if (tile >= ntiles) return;
        const float* as = smemf + (tile % 3) * G1_RAW1;
        uint32_t* aph = pa + (tile & 1) * (2 * G1_PA);
        uint32_t* apl = aph + G1_PA;
        #pragma unroll
        for (int it = 0; it < 4; it++) {         // 2048 pairs
            int i = tid + it * THREADS;
            int r = i >> 4, p = i & 15;
            float2 v = *(const float2*)(as + r * G1_SAR + 2 * p);
            uint32_t h, l;
            packpair(v.x, v.y, h, l);
            aph[r * G1_SAP + p] = h;
            apl[r * G1_SAP + p] = l;
        }
    };

    issue_tile(0); CP_COMMIT();
    issue_tile(1); CP_COMMIT();
    asm volatile("cp.async.wait_group 1;" ::: "memory");
    __syncthreads();
    convertA(0);
    __syncthreads();

    for (int t = 0; t < ntiles; t++) {
        issue_tile(t + 2);
        CP_COMMIT();
        asm volatile("cp.async.wait_group 1;" ::: "memory");

        const uint32_t* aph = pa + (t & 1) * (2 * G1_PA);
        const uint32_t* apl = aph + G1_PA;
        const uint32_t* bph = pk + (t % 3) * (2 * G1_PB);
        const uint32_t* bpl = bph + G1_PB;

        #pragma unroll
        for (int ks = 0; ks < 2; ks++) {
            const int kp0 = ks * 8;
            uint32_t fah[MT][4], fal[MT][4], fbh[NT][2], fbl[NT][2];
            #pragma unroll
            for (int mi = 0; mi < MT; mi++) {
                int r = wm + mi * 16 + g;
                fah[mi][0] = aph[r * G1_SAP + kp0 + tq];
                fah[mi][1] = aph[(r + 8) * G1_SAP + kp0 + tq];
                fah[mi][2] = aph[r * G1_SAP + kp0 + tq + 4];
                fah[mi][3] = aph[(r + 8) * G1_SAP + kp0 + tq + 4];
                fal[mi][0] = apl[r * G1_SAP + kp0 + tq];
                fal[mi][1] = apl[(r + 8) * G1_SAP + kp0 + tq];
                fal[mi][2] = apl[r * G1_SAP + kp0 + tq + 4];
                fal[mi][3] = apl[(r + 8) * G1_SAP + kp0 + tq + 4];
            }
            #pragma unroll
            for (int ni = 0; ni < NT; ni++) {
                int c = wn + ni * 8 + g;
                fbh[ni][0] = bph[(kp0 + tq) * G1_SBP + c];
                fbh[ni][1] = bph[(kp0 + tq + 4) * G1_SBP + c];
                fbl[ni][0] = bpl[(kp0 + tq) * G1_SBP + c];
                fbl[ni][1] = bpl[(kp0 + tq + 4) * G1_SBP + c];
            }
            #pragma unroll
            for (int mi = 0; mi < MT; mi++)
                #pragma unroll
                for (int ni = 0; ni < NT; ni++) {
                    MMA_BF16(acc[mi][ni], fah[mi], fbh[ni]);
                    MMA_BF16(acc[mi][ni], fal[mi], fbh[ni]);
                    MMA_BF16(acc[mi][ni], fah[mi], fbl[ni]);
                }
        }

        convertA(t + 1);
        __syncthreads();
    }

    #pragma unroll
    for (int mi = 0; mi < MT; mi++) {
        int r = row0 + wm + mi * 16 + g;
        #pragma unroll
        for (int ni = 0; ni < NT; ni++) {
            int c = wn + ni * 8 + 2 * tq;
            if (r < M)
                *(float2*)(C + (long)r * G1_BN + c) = make_float2(acc[mi][ni][0], acc[mi][ni][1]);
            if (r + 8 < M)
                *(float2*)(C + (long)(r + 8) * G1_BN + c) = make_float2(acc[mi][ni][2], acc[mi][ni][3]);
        }
    }
}

// ------------------- packed GEMM (A and B pre-split) -----------------------
// C[M,BN] = A @ B, A packed [M][KP] hi/lo u32, B packed [KP][BN] hi/lo u32.
// No conversion anywhere; 2-stage cp.async; 256 threads, 2 CTAs/SM.

constexpr int pgemm_smem_bytes(int BM, int BN) {
    int SAP = 16 + 4, SBP = BN + 8;
    return 2 * (2 * BM * SAP + 2 * 16 * SBP) * 4;
}

template <int BM, int BN, int WARPS_M, int WARPS_N, bool BIAS>
__global__ void __launch_bounds__(32 * WARPS_M * WARPS_N, 2)
packed_gemm_kernel(int M, int KP,
                   const uint32_t* __restrict__ Ah, const uint32_t* __restrict__ Al,
                   const uint32_t* __restrict__ Bh, const uint32_t* __restrict__ Bl,
                   const float* __restrict__ bias, float* __restrict__ C) {
    constexpr int THREADS = 32 * WARPS_M * WARPS_N;
    constexpr int WM = BM / WARPS_M, WN = BN / WARPS_N;
    constexpr int MT = WM / 16, NT = WN / 8;
    constexpr int BKP = 16;
    constexpr int SAP = BKP + 4, SBP = BN + 8;
    constexpr int A_ST = BM * SAP, B_ST = BKP * SBP;
    constexpr int STG = 2 * A_ST + 2 * B_ST;
    constexpr int ACH = BM * BKP / 4;        // A chunks per (hi|lo)
    constexpr int BCH = BKP * BN / 4;

    extern __shared__ uint32_t usm[];

    const int tid = threadIdx.x;
    const int warp = tid >> 5, lane = tid & 31;
    const int wm = (warp / WARPS_N) * WM;
    const int wn = (warp % WARPS_N) * WN;
    const int g = lane >> 2, tq = lane & 3;
    const int row0 = blockIdx.x * BM;
    const int ntiles = KP / BKP;

    float acc[MT][NT][4];
    #pragma unroll
    for (int mi = 0; mi < MT; mi++)
        #pragma unroll
        for (int ni = 0; ni < NT; ni++)
            #pragma unroll
            for (int q = 0; q < 4; q++) acc[mi][ni][q] = 0.f;

    auto issue_tile = [&](int tile) {
        uint32_t* ash = usm + (tile & 1) * STG;
        uint32_t* asl = ash + A_ST;
        uint32_t* bsh = asl + A_ST;
        uint32_t* bsl = bsh + B_ST;
        int p0 = tile * BKP;
        #pragma unroll
        for (int i = tid; i < ACH; i += THREADS) {
            int r = i >> 2, q = i & 3;
            int gm = row0 + r;
            int sz = (gm < M) ? 16 : 0;
            CP_ASYNC16(smem_u32(ash + r * SAP + q * 4), Ah + (long)gm * KP + p0 + q * 4, sz);
            CP_ASYNC16(smem_u32(asl + r * SAP + q * 4), Al + (long)gm * KP + p0 + q * 4, sz);
        }
        #pragma unroll
        for (int i = tid; i < BCH; i += THREADS) {
            int p = i / (BN / 4), q = i % (BN / 4);
            CP_ASYNC16(smem_u32(bsh + p * SBP + q * 4), Bh + (long)(p0 + p) * BN + q * 4, 16);
            CP_ASYNC16(smem_u32(bsl + p * SBP + q * 4), Bl + (long)(p0 + p) * BN + q * 4, 16);
        }
    };

    issue_tile(0); CP_COMMIT();

    for (int t = 0; t < ntiles; t++) {
        if (t + 1 < ntiles) {
            issue_tile(t + 1); CP_COMMIT();
            asm volatile("cp.async.wait_group 1;" ::: "memory");
        } else {
            asm volatile("cp.async.wait_group 0;" ::: "memory");
        }
        __syncthreads();

        const uint32_t* ash = usm + (t & 1) * STG;
        const uint32_t* asl = ash + A_ST;
        const uint32_t* bsh = asl + A_ST;
        const uint32_t* bsl = bsh + B_ST;

        #pragma unroll
        for (int ks = 0; ks < 2; ks++) {
            const int kp0 = ks * 8;
            uint32_t fah[MT][4], fal[MT][4], fbh[NT][2], fbl[NT][2];
            #pragma unroll
            for (int mi = 0; mi < MT; mi++) {
                int r = wm + mi * 16 + g;
                fah[mi][0] = ash[r * SAP + kp0 + tq];
                fah[mi][1] = ash[(r + 8) * SAP + kp0 + tq];
                fah[mi][2] = ash[r * SAP + kp0 + tq + 4];
                fah[mi][3] = ash[(r + 8) * SAP + kp0 + tq + 4];
                fal[mi][0] = asl[r * SAP + kp0 + tq];
                fal[mi][1] = asl[(r + 8) * SAP + kp0 + tq];
                fal[mi][2] = asl[r * SAP + kp0 + tq + 4];
                fal[mi][3] = asl[(r + 8) * SAP + kp0 + tq + 4];
            }
            #pragma unroll
            for (int ni = 0; ni < NT; ni++) {
                int c = wn + ni * 8 + g;
                fbh[ni][0] = bsh[(kp0 + tq) * SBP + c];
                fbh[ni][1] = bsh[(kp0 + tq + 4) * SBP + c];
                fbl[ni][0] = bsl[(kp0 + tq) * SBP + c];
                fbl[ni][1] = bsl[(kp0 + tq + 4) * SBP + c];
            }
            #pragma unroll
            for (int mi = 0; mi < MT; mi++)
                #pragma unroll
                for (int ni = 0; ni < NT; ni++) {
                    MMA_BF16(acc[mi][ni], fah[mi], fbh[ni]);
                    MMA_BF16(acc[mi][ni], fal[mi], fbh[ni]);
                    MMA_BF16(acc[mi][ni], fah[mi], fbl[ni]);
                }
        }
        __syncthreads();
    }

    #pragma unroll
    for (int mi = 0; mi < MT; mi++) {
        int r = row0 + wm + mi * 16 + g;
        #pragma unroll
        for (int ni = 0; ni < NT; ni++) {
            int c = wn + ni * 8 + 2 * tq;
            float bx = 0.f, by = 0.f;
            if (BIAS) { bx = bias[c]; by = bias[c + 1]; }
            if (r < M)
                *(float2*)(C + (long)r * BN + c) = make_float2(acc[mi][ni][0] + bx, acc[mi][ni][1] + by);
            if (r + 8 < M)
                *(float2*)(C + (long)(r + 8) * BN + c) = make_float2(acc[mi][ni][2] + bx, acc[mi][ni][3] + by);
        }
    }
}

// ------------------------------ CSR SpMM -----------------------------------
// spmm128: gathers fp32 support, emits PACKED hi/lo h1.

__global__ void spmm128_pk_kernel(const float* __restrict__ support,
                                  const int* __restrict__ offsets,
                                  const int* __restrict__ col,
                                  const float* __restrict__ val,
                                  const float* __restrict__ bias,
                                  uint32_t* __restrict__ outh,
                                  uint32_t* __restrict__ outl, int n) {
    int warp = (blockIdx.x * blockDim.x + threadIdx.x) >> 5;
    int lane = threadIdx.x & 31;
    if (warp >= n) return;
    int start = offsets[warp], end = offsets[warp + 1];
    const float4* sup4 = (const float4*)support;
    float4 acc = make_float4(0.f, 0.f, 0.f, 0.f);
    int j = start;
    for (; j + 2 <= end; j += 2) {
        int c0 = col[j], c1 = col[j + 1];
        float w0 = val[j], w1 = val[j + 1];
        float4 s0 = sup4[c0 * 32 + lane];
        float4 s1 = sup4[c1 * 32 + lane];
        acc.x += w0 * s0.x + w1 * s1.x;
        acc.y += w0 * s0.y + w1 * s1.y;
        acc.z += w0 * s0.z + w1 * s1.z;
        acc.w += w0 * s0.w + w1 * s1.w;
    }
    if (j < end) {
        int c = col[j]; float w = val[j];
        float4 s = sup4[c * 32 + lane];
        acc.x += w * s.x; acc.y += w * s.y; acc.z += w * s.z; acc.w += w * s.w;
    }
    float4 bb = ((const float4*)bias)[lane];
    acc.x = fmaxf(acc.x + bb.x, 0.f);
    acc.y = fmaxf(acc.y + bb.y, 0.f);
    acc.z = fmaxf(acc.z + bb.z, 0.f);
    acc.w = fmaxf(acc.w + bb.w, 0.f);
    uint32_t h0, l0, h1, l1;
    packpair(acc.x, acc.y, h0, l0);
    packpair(acc.z, acc.w, h1, l1);
    uint2 vh = make_uint2(h0, h1), vl = make_uint2(l0, l1);
    *(uint2*)(outh + warp * 64 + 2 * lane) = vh;
    *(uint2*)(outl + warp * 64 + 2 * lane) = vl;
}

// spmm64: gathers fp32 support, emits PACKED hi/lo h2.
__global__ void spmm64_pk_kernel(const float* __restrict__ support,
                                 const int* __restrict__ offsets,
                                 const int* __restrict__ col,
                                 const float* __restrict__ val,
                                 const float* __restrict__ bias,
                                 uint32_t* __restrict__ outh,
                                 uint32_t* __restrict__ outl, int n) {
    int warp = (blockIdx.x * blockDim.x + threadIdx.x) >> 5;
    int lane = threadIdx.x & 31;
    if (warp >= n) return;
    int start = offsets[warp], end = offsets[warp + 1];
    const float2* sup2 = (const float2*)support;
    float2 acc = make_float2(0.f, 0.f);
    int j = start;
    for (; j + 2 <= end; j += 2) {
        int c0 = col[j], c1 = col[j + 1];
        float w0 = val[j], w1 = val[j + 1];
        float2 s0 = sup2[c0 * 32 + lane];
        float2 s1 = sup2[c1 * 32 + lane];
        acc.x += w0 * s0.x + w1 * s1.x;
        acc.y += w0 * s0.y + w1 * s1.y;
    }
    if (j < end) {
        int c = col[j]; float w = val[j];
        float2 s = sup2[c * 32 + lane];
        acc.x += w * s.x; acc.y += w * s.y;
    }
    float2 bb = ((const float2*)bias)[lane];
    acc.x = fmaxf(acc.x + bb.x, 0.f);
    acc.y = fmaxf(acc.y + bb.y, 0.f);
    uint32_t h, l;
    packpair(acc.x, acc.y, h, l);
    outh[warp * 32 + lane] = h;
    outl[warp * 32 + lane] = l;
}

__global__ void spmm16_lsm_kernel(const float* __restrict__ support,
                                  const int* __restrict__ offsets,
                                  const int* __restrict__ col,
                                  const float* __restrict__ val,
                                  const float* __restrict__ bias,
                                  float* __restrict__ out, int n) {
    int t = blockIdx.x * blockDim.x + threadIdx.x;
    int grp = t >> 4;
    int sub = t & 15;
    bool active = grp < n;
    int g2 = active ? grp : (n - 1);
    int start = offsets[g2], end = offsets[g2 + 1];
    float acc = 0.f;
    for (int j = start; j < end; j++)
        acc += val[j] * support[col[j] * 16 + sub];
    acc += bias[sub];
    float m = acc;
    #pragma unroll
    for (int off = 8; off >= 1; off >>= 1)
        m = fmaxf(m, __shfl_xor_sync(0xffffffffu, m, off, 16));
    float s = expf(acc - m);
    #pragma unroll
    for (int off = 8; off >= 1; off >>= 1)
        s += __shfl_xor_sync(0xffffffffu, s, off, 16);
    if (active) out[grp * 16 + sub] = acc - (logf(s) + m);
}

// ------------------------------ launch -------------------------------------

extern "C" void kernel_launch(void* const* d_in, const int* in_sizes, int n_in,
                              void* d_out, int out_size) {
    const float* x  = (const float*)d_in[0];
    const float* ev = (const float*)d_in[1];
    const float* W1 = (const float*)d_in[2];
    const float* b1 = (const float*)d_in[3];
    const float* W2 = (const float*)d_in[4];
    const float* b2 = (const float*)d_in[5];
    const float* W3 = (const float*)d_in[6];
    const float* b3 = (const float*)d_in[7];
    const float* We = (const float*)d_in[8];
    const float* be = (const float*)d_in[9];
    const int* esrc = (const int*)d_in[10];
    const int* edst = (const int*)d_in[11];

    const int N = NN;
    const int E = in_sizes[10];

    float* out1 = (float*)d_out;
    float* out2 = (float*)d_out + (long)N * 16;

    float *p_support, *p_val;
    int *p_counts, *p_offsets, *p_cursor, *p_col;
    uint32_t *p_h1h, *p_h1l, *p_h2h, *p_h2l;
    uint32_t *p_w1h, *p_w1l, *p_w2h, *p_w2l, *p_w3h, *p_w3l, *p_weh, *p_wel;
    cudaGetSymbolAddress((void**)&p_support, g_support);
    cudaGetSymbolAddress((void**)&p_h1h, g_h1h);
    cudaGetSymbolAddress((void**)&p_h1l, g_h1l);
    cudaGetSymbolAddress((void**)&p_h2h, g_h2h);
    cudaGetSymbolAddress((void**)&p_h2l, g_h2l);
    cudaGetSymbolAddress((void**)&p_counts, g_counts);
    cudaGetSymbolAddress((void**)&p_offsets, g_offsets);
    cudaGetSymbolAddress((void**)&p_cursor, g_cursor);
    cudaGetSymbolAddress((void**)&p_col, g_col);
    cudaGetSymbolAddress((void**)&p_val, g_val);
    cudaGetSymbolAddress((void**)&p_w1h, g_w1h);
    cudaGetSymbolAddress((void**)&p_w1l, g_w1l);
    cudaGetSymbolAddress((void**)&p_w2h, g_w2h);
    cudaGetSymbolAddress((void**)&p_w2l, g_w2l);
    cudaGetSymbolAddress((void**)&p_w3h, g_w3h);
    cudaGetSymbolAddress((void**)&p_w3l, g_w3l);
    cudaGetSymbolAddress((void**)&p_weh, g_weh);
    cudaGetSymbolAddress((void**)&p_wel, g_wel);

    constexpr int S2 = pgemm_smem_bytes(128, 64);   // ~59.4KB
    constexpr int S3 = pgemm_smem_bytes(128, 16);   // ~47.1KB
    cudaFuncSetAttribute(gemm1_packed_kernel,
                         cudaFuncAttributeMaxDynamicSharedMemorySize, G1_SMEM);
    cudaFuncSetAttribute(packed_gemm_kernel<128, 64, 4, 2, false>,
                         cudaFuncAttributeMaxDynamicSharedMemorySize, S2);
    cudaFuncSetAttribute(packed_gemm_kernel<128, 64, 4, 2, true>,
                         cudaFuncAttributeMaxDynamicSharedMemorySize, S2);
    cudaFuncSetAttribute(packed_gemm_kernel<128, 16, 8, 1, false>,
                         cudaFuncAttributeMaxDynamicSharedMemorySize, S3);

    // ---- weight pre-split + CSR build ----
    weight_split_kernel<<<(256 * 128 + 255) / 256, 256>>>(W1, p_w1h, p_w1l, 500, 128, 256);
    weight_split_kernel<<<(64 * 64 + 255) / 256, 256>>>(W2, p_w2h, p_w2l, 128, 64, 64);
    weight_split_kernel<<<(32 * 16 + 255) / 256, 256>>>(W3, p_w3h, p_w3l, 64, 16, 32);
    weight_split_kernel<<<(32 * 64 + 255) / 256, 256>>>(We, p_weh, p_wel, 64, 64, 32);

    cudaMemsetAsync(p_counts, 0, (N + 1) * sizeof(int), 0);
    cudaMemsetAsync(p_cursor, 0, N * sizeof(int), 0);
    hist_kernel<<<(E + 255) / 256, 256>>>(esrc, p_counts, E);
    scan_kernel<<<1, 1024>>>(p_counts, p_offsets, N);
    scatter_kernel<<<(E + 255) / 256, 256>>>(esrc, edst, ev, p_offsets, p_cursor, p_col, p_val, E);

    // ---- layer 1: support = x@W1 [N,128]; h1 = packed(relu(agg + b1)) ----
    gemm1_packed_kernel<<<(N + 127) / 128, 512, G1_SMEM>>>(N, 500, x, p_w1h, p_w1l, p_support);
    spmm128_pk_kernel<<<(N * 32 + 255) / 256, 256>>>(p_support, p_offsets, p_col, p_val, b1, p_h1h, p_h1l, N);

    // ---- layer 2: support = h1@W2 [N,64]; h2 = packed(relu(agg + b2)) ----
    packed_gemm_kernel<128, 64, 4, 2, false><<<(N + 127) / 128, 256, S2>>>(
        N, 64, p_h1h, p_h1l, p_w2h, p_w2l, nullptr, p_support);
    spmm64_pk_kernel<<<(N * 32 + 255) / 256, 256>>>(p_support, p_offsets, p_col, p_val, b2, p_h2h, p_h2l, N);

    // ---- layer 3: support = h2@W3 [N,16]; out1 = log_softmax(agg + b3) ----
    packed_gemm_kernel<128, 16, 8, 1, false><<<(N + 127) / 128, 256, S3>>>(
        N, 32, p_h2h, p_h2l, p_w3h, p_w3l, nullptr, p_support);
    spmm16_lsm_kernel<<<(N * 16 + 255) / 256, 256>>>(p_support, p_offsets, p_col, p_val, b3, out1, N);

    // ---- head 2: out2 = h2@We + be ----
    packed_gemm_kernel<128, 64, 4, 2, true><<<(N + 127) / 128, 256, S2>>>(
        N, 32, p_h2h, p_h2l, p_weh, p_wel, be, out2);
}

// round 15
// speedup vs baseline: 1.1193x; 1.0955x over previous
#include <cuda_runtime.h>
#include <cuda_bf16.h>
#include <cstdint>
#include <stdint.h>
#include <math.h>

// ---------------------------------------------------------------------------
// GCN 3-layer. Round 14: GEMM1 = single-pass tf32 mma (no split, no convert;
// 3x less tensor work, accuracy budget spent: expect ~1e-4 rel_err),
// BM=64 / 256thr / 2 CTAs/SM. Layers 2/3/e keep exact 3-term packed-bf16
// path (weights pre-split; SpMM emits packed h1/h2).
// ---------------------------------------------------------------------------

#define NN 50000
#define EE 800000

__device__ float g_support[NN * 128];
__device__ uint32_t g_h1h[NN * 64];
__device__ uint32_t g_h1l[NN * 64];
__device__ uint32_t g_h2h[NN * 32];
__device__ uint32_t g_h2l[NN * 32];
__device__ int   g_counts[NN + 1];
__device__ int   g_offsets[NN + 1];
__device__ int   g_cursor[NN];
__device__ int   g_col[EE];
__device__ float g_val[EE];
// packed weights: [K/2][N] bf16x2 hi/lo
__device__ uint32_t g_w2h[64 * 64],  g_w2l[64 * 64];      // K=128
__device__ uint32_t g_w3h[32 * 16],  g_w3l[32 * 16];      // K=64
__device__ uint32_t g_weh[32 * 64],  g_wel[32 * 64];      // K=64

__device__ __forceinline__ uint32_t smem_u32(const void* p) {
    uint32_t a;
    asm("{ .reg .u64 t; cvta.to.shared.u64 t, %1; cvt.u32.u64 %0, t; }" : "=r"(a) : "l"(p));
    return a;
}

__device__ __forceinline__ uint32_t f2tf32(float x) {
    uint32_t r;
    asm("cvt.rna.tf32.f32 %0, %1;" : "=r"(r) : "f"(x));
    return r;
}

// pack (x=k_even, y=k_odd) -> hi bf16x2 and lo (residual) bf16x2
__device__ __forceinline__ void packpair(float x, float y, uint32_t& h, uint32_t& l) {
    uint32_t p;
    asm("cvt.rn.bf16x2.f32 %0, %1, %2;" : "=r"(p) : "f"(y), "f"(x));
    float xr = __uint_as_float(p << 16);
    float yr = __uint_as_float(p & 0xffff0000u);
    uint32_t q;
    asm("cvt.rn.bf16x2.f32 %0, %1, %2;" : "=r"(q) : "f"(y - yr), "f"(x - xr));
    h = p; l = q;
}

#define MMA_BF16(c, a, b)                                                    \
    asm volatile(                                                            \
        "mma.sync.aligned.m16n8k16.row.col.f32.bf16.bf16.f32 "               \
        "{%0,%1,%2,%3}, {%4,%5,%6,%7}, {%8,%9}, {%0,%1,%2,%3};\n"            \
        : "+f"((c)[0]), "+f"((c)[1]), "+f"((c)[2]), "+f"((c)[3])             \
        : "r"((a)[0]), "r"((a)[1]), "r"((a)[2]), "r"((a)[3]),                \
          "r"((b)[0]), "r"((b)[1]))

#define MMA_TF32(c, a, b)                                                    \
    asm volatile(                                                            \
        "mma.sync.aligned.m16n8k8.row.col.f32.tf32.tf32.f32 "                \
        "{%0,%1,%2,%3}, {%4,%5,%6,%7}, {%8,%9}, {%0,%1,%2,%3};\n"            \
        : "+f"((c)[0]), "+f"((c)[1]), "+f"((c)[2]), "+f"((c)[3])             \
        : "r"((a)[0]), "r"((a)[1]), "r"((a)[2]), "r"((a)[3]),                \
          "r"((b)[0]), "r"((b)[1]))

#define CP_ASYNC16(dst, src, sz) \
    asm volatile("cp.async.cg.shared.global [%0], [%1], 16, %2;" \
                 :: "r"(dst), "l"(src), "r"(sz))
#define CP_COMMIT() asm volatile("cp.async.commit_group;" ::: "memory")

// ------------------------------ weight split -------------------------------

__global__ void weight_split_kernel(const float* __restrict__ W,
                                    uint32_t* __restrict__ Wh, uint32_t* __restrict__ Wl,
                                    int K, int N, int KPtot) {
    int i = blockIdx.x * blockDim.x + threadIdx.x;
    if (i >= KPtot * N) return;
    int p = i / N, n = i % N;
    int k0 = 2 * p;
    float v0 = (k0 < K) ? W[(long)k0 * N + n] : 0.f;
    float v1 = (k0 + 1 < K) ? W[(long)(k0 + 1) * N + n] : 0.f;
    uint32_t h, l;
    packpair(v0, v1, h, l);
    Wh[i] = h; Wl[i] = l;
}

// ------------------------------ CSR build ----------------------------------

__global__ void hist_kernel(const int* __restrict__ src, int* __restrict__ counts, int E) {
    int i = blockIdx.x * blockDim.x + threadIdx.x;
    if (i < E) atomicAdd(&counts[src[i]], 1);
}

__global__ void scan_kernel(const int* __restrict__ counts, int* __restrict__ offsets, int n) {
    const int T = 1024;
    __shared__ int wsum[32];
    int tid = threadIdx.x;
    int per = (n + T - 1) / T;
    int beg = tid * per;
    int end = min(beg + per, n);
    int sum = 0;
    for (int i = beg; i < end; i++) sum += counts[i];
    int lane = tid & 31, wid = tid >> 5;
    int v = sum;
    #pragma unroll
    for (int off = 1; off < 32; off <<= 1) {
        int t2 = __shfl_up_sync(0xffffffffu, v, off);
        if (lane >= off) v += t2;
    }
    if (lane == 31) wsum[wid] = v;
    __syncthreads();
    if (wid == 0) {
        int w = wsum[lane];
        #pragma unroll
        for (int off = 1; off < 32; off <<= 1) {
            int t2 = __shfl_up_sync(0xffffffffu, w, off);
            if (lane >= off) w += t2;
        }
        wsum[lane] = w;
    }
    __syncthreads();
    int pre = v - sum + (wid > 0 ? wsum[wid - 1] : 0);
    int run = pre;
    for (int i = beg; i < end; i++) { offsets[i] = run; run += counts[i]; }
    if (end == n) offsets[n] = run;
}

__global__ void scatter_kernel(const int* __restrict__ src, const int* __restrict__ dst,
                               const float* __restrict__ ev,
                               const int* __restrict__ offsets, int* __restrict__ cursor,
                               int* __restrict__ col, float* __restrict__ val, int E) {
    int i = blockIdx.x * blockDim.x + threadIdx.x;
    if (i < E) {
        int s = src[i];
        int pos = offsets[s] + atomicAdd(&cursor[s], 1);
        col[pos] = dst[i];
        val[pos] = ev[i];
    }
}

// ------------------- GEMM1: single-pass tf32 (BM=64, 2 CTA/SM) -------------
// C[M,128] = A[M,K] @ B[K,128], fp32 in, tf32 mma, fp32 out.

static constexpr int T1_BM = 64, T1_BN = 128, T1_BK = 32, T1_NST = 3;
static constexpr int T1_SA = T1_BK + 4;      // 36
static constexpr int T1_SB = T1_BN + 8;      // 136 (conflict-free: 136 % 32 == 8)
static constexpr int T1_AST = T1_BM * T1_SA; // 2304 f32
static constexpr int T1_BST = T1_BK * T1_SB; // 4352 f32
static constexpr int T1_SMEM = T1_NST * (T1_AST + T1_BST) * 4;  // 79872 B

__global__ void __launch_bounds__(256, 2)
gemm1_tf32_kernel(int M, int K,
                  const float* __restrict__ A, const float* __restrict__ B,
                  float* __restrict__ C) {
    constexpr int THREADS = 256;
    constexpr int MT = 2, NT = 4;  // warps 2x4, WM=32, WN=32
    extern __shared__ float smemf[];

    const int tid = threadIdx.x;
    const int warp = tid >> 5, lane = tid & 31;
    const int wm = (warp >> 2) * 32;
    const int wn = (warp & 3) * 32;
    const int g = lane >> 2, t = lane & 3;
    const int row0 = blockIdx.x * T1_BM;
    const int ntiles = (K + T1_BK - 1) / T1_BK;

    float acc[MT][NT][4];
    #pragma unroll
    for (int mi = 0; mi < MT; mi++)
        #pragma unroll
        for (int ni = 0; ni < NT; ni++)
            #pragma unroll
            for (int q = 0; q < 4; q++) acc[mi][ni][q] = 0.f;

    auto issue_tile = [&](int tile) {
        if (tile >= ntiles) return;
        int k0 = tile * T1_BK;
        float* as = smemf + (tile % T1_NST) * (T1_AST + T1_BST);
        float* bs = as + T1_AST;
        #pragma unroll
        for (int it = 0; it < 2; it++) {            // 512 A chunks
            int i = tid + it * THREADS;
            int r = i >> 3, q = i & 7;
            int gm = row0 + r, gk = k0 + q * 4;
            uint32_t dst = smem_u32(as + r * T1_SA + q * 4);
            const float* src = A + (long)gm * K + gk;
            int sz = (gm < M && gk + 4 <= K) ? 16 : 0;
            CP_ASYNC16(dst, src, sz);
        }
        #pragma unroll
        for (int it = 0; it < 4; it++) {            // 1024 B chunks
            int i = tid + it * THREADS;
            int r = i >> 5, q = i & 31;
            int gk = k0 + r;
            uint32_t dst = smem_u32(bs + r * T1_SB + q * 4);
            const float* src = B + (long)gk * T1_BN + q * 4;
            int sz = (gk < K) ? 16 : 0;
            CP_ASYNC16(dst, src, sz);
        }
    };

    #pragma unroll
    for (int s = 0; s < T1_NST - 1; s++) { issue_tile(s); CP_COMMIT(); }

    for (int tt = 0; tt < ntiles; tt++) {
        asm volatile("cp.async.wait_group %0;" :: "n"(T1_NST - 2) : "memory");
        __syncthreads();
        issue_tile(tt + T1_NST - 1);
        CP_COMMIT();

        const float* as = smemf + (tt % T1_NST) * (T1_AST + T1_BST);
        const float* bs = as + T1_AST;

        #pragma unroll
        for (int kk = 0; kk < T1_BK; kk += 8) {
            uint32_t fa[MT][4], fb[NT][2];
            #pragma unroll
            for (int mi = 0; mi < MT; mi++) {
                int r = wm + mi * 16 + g;
                fa[mi][0] = f2tf32(as[r * T1_SA + kk + t]);
                fa[mi][1] = f2tf32(as[(r + 8) * T1_SA + kk + t]);
                fa[mi][2] = f2tf32(as[r * T1_SA + kk + t + 4]);
                fa[mi][3] = f2tf32(as[(r + 8) * T1_SA + kk + t + 4]);
            }
            #pragma unroll
            for (int ni = 0; ni < NT; ni++) {
                int c = wn + ni * 8 + g;
                fb[ni][0] = f2tf32(bs[(kk + t) * T1_SB + c]);
                fb[ni][1] = f2tf32(bs[(kk + t + 4) * T1_SB + c]);
            }
            #pragma unroll
            for (int mi = 0; mi < MT; mi++)
                #pragma unroll
                for (int ni = 0; ni < NT; ni++)
                    MMA_TF32(acc[mi][ni], fa[mi], fb[ni]);
        }
        __syncthreads();
    }

    #pragma unroll
    for (int mi = 0; mi < MT; mi++) {
        int r = row0 + wm + mi * 16 + g;
        #pragma unroll
        for (int ni = 0; ni < NT; ni++) {
            int c = wn + ni * 8 + 2 * t;
            if (r < M)
                *(float2*)(C + (long)r * T1_BN + c) = make_float2(acc[mi][ni][0], acc[mi][ni][1]);
            if (r + 8 < M)
                *(float2*)(C + (long)(r + 8) * T1_BN + c) = make_float2(acc[mi][ni][2], acc[mi][ni][3]);
        }
    }
}

// ------------------- packed GEMM (A and B pre-split bf16) ------------------

constexpr int pgemm_smem_bytes(int BM, int BN) {
    int SAP = 16 + 4, SBP = BN + 8;
    return 2 * (2 * BM * SAP + 2 * 16 * SBP) * 4;
}

template <int BM, int BN, int WARPS_M, int WARPS_N, bool BIAS>
__global__ void __launch_bounds__(32 * WARPS_M * WARPS_N, 2)
packed_gemm_kernel(int M, int KP,
                   const uint32_t* __restrict__ Ah, const uint32_t* __restrict__ Al,
                   const uint32_t* __restrict__ Bh, const uint32_t* __restrict__ Bl,
                   const float* __restrict__ bias, float* __restrict__ C) {
    constexpr int THREADS = 32 * WARPS_M * WARPS_N;
    constexpr int WM = BM / WARPS_M, WN = BN / WARPS_N;
    constexpr int MT = WM / 16, NT = WN / 8;
    constexpr int BKP = 16;
    constexpr int SAP = BKP + 4, SBP = BN + 8;
    constexpr int A_ST = BM * SAP, B_ST = BKP * SBP;
    constexpr int STG = 2 * A_ST + 2 * B_ST;
    constexpr int ACH = BM * BKP / 4;
    constexpr int BCH = BKP * BN / 4;

    extern __shared__ uint32_t usm[];

    const int tid = threadIdx.x;
    const int warp = tid >> 5, lane = tid & 31;
    const int wm = (warp / WARPS_N) * WM;
    const int wn = (warp % WARPS_N) * WN;
    const int g = lane >> 2, tq = lane & 3;
    const int row0 = blockIdx.x * BM;
    const int ntiles = KP / BKP;

    float acc[MT][NT][4];
    #pragma unroll
    for (int mi = 0; mi < MT; mi++)
        #pragma unroll
        for (int ni = 0; ni < NT; ni++)
            #pragma unroll
            for (int q = 0; q < 4; q++) acc[mi][ni][q] = 0.f;

    auto issue_tile = [&](int tile) {
        uint32_t* ash = usm + (tile & 1) * STG;
        uint32_t* asl = ash + A_ST;
        uint32_t* bsh = asl + A_ST;
        uint32_t* bsl = bsh + B_ST;
        int p0 = tile * BKP;
        #pragma unroll
        for (int i = tid; i < ACH; i += THREADS) {
            int r = i >> 2, q = i & 3;
            int gm = row0 + r;
            int sz = (gm < M) ? 16 : 0;
            CP_ASYNC16(smem_u32(ash + r * SAP + q * 4), Ah + (long)gm * KP + p0 + q * 4, sz);
            CP_ASYNC16(smem_u32(asl + r * SAP + q * 4), Al + (long)gm * KP + p0 + q * 4, sz);
        }
        #pragma unroll
        for (int i = tid; i < BCH; i += THREADS) {
            int p = i / (BN / 4), q = i % (BN / 4);
            CP_ASYNC16(smem_u32(bsh + p * SBP + q * 4), Bh + (long)(p0 + p) * BN + q * 4, 16);
            CP_ASYNC16(smem_u32(bsl + p * SBP + q * 4), Bl + (long)(p0 + p) * BN + q * 4, 16);
        }
    };

    issue_tile(0); CP_COMMIT();

    for (int t = 0; t < ntiles; t++) {
        if (t + 1 < ntiles) {
            issue_tile(t + 1); CP_COMMIT();
            asm volatile("cp.async.wait_group 1;" ::: "memory");
        } else {
            asm volatile("cp.async.wait_group 0;" ::: "memory");
        }
        __syncthreads();

        const uint32_t* ash = usm + (t & 1) * STG;
        const uint32_t* asl = ash + A_ST;
        const uint32_t* bsh = asl + A_ST;
        const uint32_t* bsl = bsh + B_ST;

        #pragma unroll
        for (int ks = 0; ks < 2; ks++) {
            const int kp0 = ks * 8;
            uint32_t fah[MT][4], fal[MT][4], fbh[NT][2], fbl[NT][2];
            #pragma unroll
            for (int mi = 0; mi < MT; mi++) {
                int r = wm + mi * 16 + g;
                fah[mi][0] = ash[r * SAP + kp0 + tq];
                fah[mi][1] = ash[(r + 8) * SAP + kp0 + tq];
                fah[mi][2] = ash[r * SAP + kp0 + tq + 4];
                fah[mi][3] = ash[(r + 8) * SAP + kp0 + tq + 4];
                fal[mi][0] = asl[r * SAP + kp0 + tq];
                fal[mi][1] = asl[(r + 8) * SAP + kp0 + tq];
                fal[mi][2] = asl[r * SAP + kp0 + tq + 4];
                fal[mi][3] = asl[(r + 8) * SAP + kp0 + tq + 4];
            }
            #pragma unroll
            for (int ni = 0; ni < NT; ni++) {
                int c = wn + ni * 8 + g;
                fbh[ni][0] = bsh[(kp0 + tq) * SBP + c];
                fbh[ni][1] = bsh[(kp0 + tq + 4) * SBP + c];
                fbl[ni][0] = bsl[(kp0 + tq) * SBP + c];
                fbl[ni][1] = bsl[(kp0 + tq + 4) * SBP + c];
            }
            #pragma unroll
            for (int mi = 0; mi < MT; mi++)
                #pragma unroll
                for (int ni = 0; ni < NT; ni++) {
                    MMA_BF16(acc[mi][ni], fah[mi], fbh[ni]);
                    MMA_BF16(acc[mi][ni], fal[mi], fbh[ni]);
                    MMA_BF16(acc[mi][ni], fah[mi], fbl[ni]);
                }
        }
        __syncthreads();
    }

    #pragma unroll
    for (int mi = 0; mi < MT; mi++) {
        int r = row0 + wm + mi * 16 + g;
        #pragma unroll
        for (int ni = 0; ni < NT; ni++) {
            int c = wn + ni * 8 + 2 * tq;
            float bx = 0.f, by = 0.f;
            if (BIAS) { bx = bias[c]; by = bias[c + 1]; }
            if (r < M)
                *(float2*)(C + (long)r * BN + c) = make_float2(acc[mi][ni][0] + bx, acc[mi][ni][1] + by);
            if (r + 8 < M)
                *(float2*)(C + (long)(r + 8) * BN + c) = make_float2(acc[mi][ni][2] + bx, acc[mi][ni][3] + by);
        }
    }
}

// ------------------------------ CSR SpMM -----------------------------------

__global__ void spmm128_pk_kernel(const float* __restrict__ support,
                                  const int* __restrict__ offsets,
                                  const int* __restrict__ col,
                                  const float* __restrict__ val,
                                  const float* __restrict__ bias,
                                  uint32_t* __restrict__ outh,
                                  uint32_t* __restrict__ outl, int n) {
    int warp = (blockIdx.x * blockDim.x + threadIdx.x) >> 5;
    int lane = threadIdx.x & 31;
    if (warp >= n) return;
    int start = offsets[warp], end = offsets[warp + 1];
    const float4* sup4 = (const float4*)support;
    float4 acc = make_float4(0.f, 0.f, 0.f, 0.f);
    int j = start;
    for (; j + 2 <= end; j += 2) {
        int c0 = col[j], c1 = col[j + 1];
        float w0 = val[j], w1 = val[j + 1];
        float4 s0 = sup4[c0 * 32 + lane];
        float4 s1 = sup4[c1 * 32 + lane];
        acc.x += w0 * s0.x + w1 * s1.x;
        acc.y += w0 * s0.y + w1 * s1.y;
        acc.z += w0 * s0.z + w1 * s1.z;
        acc.w += w0 * s0.w + w1 * s1.w;
    }
    if (j < end) {
        int c = col[j]; float w = val[j];
        float4 s = sup4[c * 32 + lane];
        acc.x += w * s.x; acc.y += w * s.y; acc.z += w * s.z; acc.w += w * s.w;
    }
    float4 bb = ((const float4*)bias)[lane];
    acc.x = fmaxf(acc.x + bb.x, 0.f);
    acc.y = fmaxf(acc.y + bb.y, 0.f);
    acc.z = fmaxf(acc.z + bb.z, 0.f);
    acc.w = fmaxf(acc.w + bb.w, 0.f);
    uint32_t h0, l0, h1, l1;
    packpair(acc.x, acc.y, h0, l0);
    packpair(acc.z, acc.w, h1, l1);
    *(uint2*)(outh + warp * 64 + 2 * lane) = make_uint2(h0, h1);
    *(uint2*)(outl + warp * 64 + 2 * lane) = make_uint2(l0, l1);
}

__global__ void spmm64_pk_kernel(const float* __restrict__ support,
                                 const int* __restrict__ offsets,
                                 const int* __restrict__ col,
                                 const float* __restrict__ val,
                                 const float* __restrict__ bias,
                                 uint32_t* __restrict__ outh,
                                 uint32_t* __restrict__ outl, int n) {
    int warp = (blockIdx.x * blockDim.x + threadIdx.x) >> 5;
    int lane = threadIdx.x & 31;
    if (warp >= n) return;
    int start = offsets[warp], end = offsets[warp + 1];
    const float2* sup2 = (const float2*)support;
    float2 acc = make_float2(0.f, 0.f);
    int j = start;
    for (; j + 2 <= end; j += 2) {
        int c0 = col[j], c1 = col[j + 1];
        float w0 = val[j], w1 = val[j + 1];
        float2 s0 = sup2[c0 * 32 + lane];
        float2 s1 = sup2[c1 * 32 + lane];
        acc.x += w0 * s0.x + w1 * s1.x;
        acc.y += w0 * s0.y + w1 * s1.y;
    }
    if (j < end) {
        int c = col[j]; float w = val[j];
        float2 s = sup2[c * 32 + lane];
        acc.x += w * s.x; acc.y += w * s.y;
    }
    float2 bb = ((const float2*)bias)[lane];
    acc.x = fmaxf(acc.x + bb.x, 0.f);
    acc.y = fmaxf(acc.y + bb.y, 0.f);
    uint32_t h, l;
    packpair(acc.x, acc.y, h, l);
    outh[warp * 32 + lane] = h;
    outl[warp * 32 + lane] = l;
}

__global__ void spmm16_lsm_kernel(const float* __restrict__ support,
                                  const int* __restrict__ offsets,
                                  const int* __restrict__ col,
                                  const float* __restrict__ val,
                                  const float* __restrict__ bias,
                                  float* __restrict__ out, int n) {
    int t = blockIdx.x * blockDim.x + threadIdx.x;
    int grp = t >> 4;
    int sub = t & 15;
    bool active = grp < n;
    int g2 = active ? grp : (n - 1);
    int start = offsets[g2], end = offsets[g2 + 1];
    float acc = 0.f;
    for (int j = start; j < end; j++)
        acc += val[j] * support[col[j] * 16 + sub];
    acc += bias[sub];
    float m = acc;
    #pragma unroll
    for (int off = 8; off >= 1; off >>= 1)
        m = fmaxf(m, __shfl_xor_sync(0xffffffffu, m, off, 16));
    float s = expf(acc - m);
    #pragma unroll
    for (int off = 8; off >= 1; off >>= 1)
        s += __shfl_xor_sync(0xffffffffu, s, off, 16);
    if (active) out[grp * 16 + sub] = acc - (logf(s) + m);
}

// ------------------------------ launch -------------------------------------

extern "C" void kernel_launch(void* const* d_in, const int* in_sizes, int n_in,
                              void* d_out, int out_size) {
    const float* x  = (const float*)d_in[0];
    const float* ev = (const float*)d_in[1];
    const float* W1 = (const float*)d_in[2];
    const float* b1 = (const float*)d_in[3];
    const float* W2 = (const float*)d_in[4];
    const float* b2 = (const float*)d_in[5];
    const float* W3 = (const float*)d_in[6];
    const float* b3 = (const float*)d_in[7];
    const float* We = (const float*)d_in[8];
    const float* be = (const float*)d_in[9];
    const int* esrc = (const int*)d_in[10];
    const int* edst = (const int*)d_in[11];

    const int N = NN;
    const int E = in_sizes[10];

    float* out1 = (float*)d_out;
    float* out2 = (float*)d_out + (long)N * 16;

    float *p_support, *p_val;
    int *p_counts, *p_offsets, *p_cursor, *p_col;
    uint32_t *p_h1h, *p_h1l, *p_h2h, *p_h2l;
    uint32_t *p_w2h, *p_w2l, *p_w3h, *p_w3l, *p_weh, *p_wel;
    cudaGetSymbolAddress((void**)&p_support, g_support);
    cudaGetSymbolAddress((void**)&p_h1h, g_h1h);
    cudaGetSymbolAddress((void**)&p_h1l, g_h1l);
    cudaGetSymbolAddress((void**)&p_h2h, g_h2h);
    cudaGetSymbolAddress((void**)&p_h2l, g_h2l);
    cudaGetSymbolAddress((void**)&p_counts, g_counts);
    cudaGetSymbolAddress((void**)&p_offsets, g_offsets);
    cudaGetSymbolAddress((void**)&p_cursor, g_cursor);
    cudaGetSymbolAddress((void**)&p_col, g_col);
    cudaGetSymbolAddress((void**)&p_val, g_val);
    cudaGetSymbolAddress((void**)&p_w2h, g_w2h);
    cudaGetSymbolAddress((void**)&p_w2l, g_w2l);
    cudaGetSymbolAddress((void**)&p_w3h, g_w3h);
    cudaGetSymbolAddress((void**)&p_w3l, g_w3l);
    cudaGetSymbolAddress((void**)&p_weh, g_weh);
    cudaGetSymbolAddress((void**)&p_wel, g_wel);

    constexpr int S2 = pgemm_smem_bytes(128, 64);
    constexpr int S3 = pgemm_smem_bytes(128, 16);
    cudaFuncSetAttribute(gemm1_tf32_kernel,
                         cudaFuncAttributeMaxDynamicSharedMemorySize, T1_SMEM);
    cudaFuncSetAttribute(packed_gemm_kernel<128, 64, 4, 2, false>,
                         cudaFuncAttributeMaxDynamicSharedMemorySize, S2);
    cudaFuncSetAttribute(packed_gemm_kernel<128, 64, 4, 2, true>,
                         cudaFuncAttributeMaxDynamicSharedMemorySize, S2);
    cudaFuncSetAttribute(packed_gemm_kernel<128, 16, 8, 1, false>,
                         cudaFuncAttributeMaxDynamicSharedMemorySize, S3);

    // ---- weight pre-split (W2/W3/We) + CSR build ----
    weight_split_kernel<<<(64 * 64 + 255) / 256, 256>>>(W2, p_w2h, p_w2l, 128, 64, 64);
    weight_split_kernel<<<(32 * 16 + 255) / 256, 256>>>(W3, p_w3h, p_w3l, 64, 16, 32);
    weight_split_kernel<<<(32 * 64 + 255) / 256, 256>>>(We, p_weh, p_wel, 64, 64, 32);

    cudaMemsetAsync(p_counts, 0, (N + 1) * sizeof(int), 0);
    cudaMemsetAsync(p_cursor, 0, N * sizeof(int), 0);
    hist_kernel<<<(E + 255) / 256, 256>>>(esrc, p_counts, E);
    scan_kernel<<<1, 1024>>>(p_counts, p_offsets, N);
    scatter_kernel<<<(E + 255) / 256, 256>>>(esrc, edst, ev, p_offsets, p_cursor, p_col, p_val, E);

    // ---- layer 1: support = x@W1 [N,128] (tf32); h1 = packed(relu(agg+b1)) ----
    gemm1_tf32_kernel<<<(N + T1_BM - 1) / T1_BM, 256, T1_SMEM>>>(N, 500, x, W1, p_support);
    spmm128_pk_kernel<<<(N * 32 + 255) / 256, 256>>>(p_support, p_offsets, p_col, p_val, b1, p_h1h, p_h1l, N);

    // ---- layer 2: support = h1@W2 [N,64]; h2 = packed(relu(agg + b2)) ----
    packed_gemm_kernel<128, 64, 4, 2, false><<<(N + 127) / 128, 256, S2>>>(
        N, 64, p_h1h, p_h1l, p_w2h, p_w2l, nullptr, p_support);
    spmm64_pk_kernel<<<(N * 32 + 255) / 256, 256>>>(p_support, p_offsets, p_col, p_val, b2, p_h2h, p_h2l, N);

    // ---- layer 3: support = h2@W3 [N,16]; out1 = log_softmax(agg + b3) ----
    packed_gemm_kernel<128, 16, 8, 1, false><<<(N + 127) / 128, 256, S3>>>(
        N, 32, p_h2h, p_h2l, p_w3h, p_w3l, nullptr, p_support);
    spmm16_lsm_kernel<<<(N * 16 + 255) / 256, 256>>>(p_support, p_offsets, p_col, p_val, b3, out1, N);

    // ---- head 2: out2 = h2@We + be ----
    packed_gemm_kernel<128, 64, 4, 2, true><<<(N + 127) / 128, 256, S2>>>(
        N, 32, p_h2h, p_h2l, p_weh, p_wel, be, out2);
}

// round 16
// speedup vs baseline: 1.1392x; 1.0178x over previous
#include <cuda_runtime.h>
#include <cuda_bf16.h>
#include <cstdint>
#include <stdint.h>
#include <math.h>

// ---------------------------------------------------------------------------
// GCN 3-layer. Round 15: ALL dense GEMMs = single-pass tf32 mma.sync
// (convert-on-read, cp.async 3-stage, 2 CTAs/SM). No weight pre-split, no
// packed intermediates: h1/h2 fp32, SpMM epilogues fused bias+ReLU.
// CSR build (vectorized hist) + gather SpMM + fused spmm16+log_softmax.
// Accuracy: ~1e-4 per tf32 layer, total ~2-4e-4 << 1e-3 threshold.
// ---------------------------------------------------------------------------

#define NN 50000
#define EE 800000

__device__ float g_support[NN * 128];
__device__ float g_h1[NN * 128];
__device__ float g_h2[NN * 64];
__device__ int   g_counts[NN + 1];
__device__ int   g_offsets[NN + 1];
__device__ int   g_cursor[NN];
__device__ int   g_col[EE];
__device__ float g_val[EE];

__device__ __forceinline__ uint32_t smem_u32(const void* p) {
    uint32_t a;
    asm("{ .reg .u64 t; cvta.to.shared.u64 t, %1; cvt.u32.u64 %0, t; }" : "=r"(a) : "l"(p));
    return a;
}
__device__ __forceinline__ uint32_t f2tf32(float x) {
    uint32_t r;
    asm("cvt.rna.tf32.f32 %0, %1;" : "=r"(r) : "f"(x));
    return r;
}

#define MMA_TF32(c, a, b)                                                    \
    asm volatile(                                                            \
        "mma.sync.aligned.m16n8k8.row.col.f32.tf32.tf32.f32 "                \
        "{%0,%1,%2,%3}, {%4,%5,%6,%7}, {%8,%9}, {%0,%1,%2,%3};\n"            \
        : "+f"((c)[0]), "+f"((c)[1]), "+f"((c)[2]), "+f"((c)[3])             \
        : "r"((a)[0]), "r"((a)[1]), "r"((a)[2]), "r"((a)[3]),                \
          "r"((b)[0]), "r"((b)[1]))

#define CP_ASYNC16(dst, src, sz) \
    asm volatile("cp.async.cg.shared.global [%0], [%1], 16, %2;" \
                 :: "r"(dst), "l"(src), "r"(sz))
#define CP_COMMIT() asm volatile("cp.async.commit_group;" ::: "memory")

// ------------------------------ CSR build ----------------------------------

__global__ void hist_kernel(const int4* __restrict__ src4, int* __restrict__ counts, int E4) {
    int i = blockIdx.x * blockDim.x + threadIdx.x;
    if (i < E4) {
        int4 v = src4[i];
        atomicAdd(&counts[v.x], 1);
        atomicAdd(&counts[v.y], 1);
        atomicAdd(&counts[v.z], 1);
        atomicAdd(&counts[v.w], 1);
    }
}

__global__ void scan_kernel(const int* __restrict__ counts, int* __restrict__ offsets, int n) {
    const int T = 1024;
    __shared__ int wsum[32];
    int tid = threadIdx.x;
    int per = (n + T - 1) / T;
    int beg = tid * per;
    int end = min(beg + per, n);
    int sum = 0;
    for (int i = beg; i < end; i++) sum += counts[i];
    int lane = tid & 31, wid = tid >> 5;
    int v = sum;
    #pragma unroll
    for (int off = 1; off < 32; off <<= 1) {
        int t2 = __shfl_up_sync(0xffffffffu, v, off);
        if (lane >= off) v += t2;
    }
    if (lane == 31) wsum[wid] = v;
    __syncthreads();
    if (wid == 0) {
        int w = wsum[lane];
        #pragma unroll
        for (int off = 1; off < 32; off <<= 1) {
            int t2 = __shfl_up_sync(0xffffffffu, w, off);
            if (lane >= off) w += t2;
        }
        wsum[lane] = w;
    }
    __syncthreads();
    int pre = v - sum + (wid > 0 ? wsum[wid - 1] : 0);
    int run = pre;
    for (int i = beg; i < end; i++) { offsets[i] = run; run += counts[i]; }
    if (end == n) offsets[n] = run;
}

__global__ void scatter_kernel(const int* __restrict__ src, const int* __restrict__ dst,
                               const float* __restrict__ ev,
                               const int* __restrict__ offsets, int* __restrict__ cursor,
                               int* __restrict__ col, float* __restrict__ val, int E) {
    int i = blockIdx.x * blockDim.x + threadIdx.x;
    if (i < E) {
        int s = src[i];
        int pos = offsets[s] + atomicAdd(&cursor[s], 1);
        col[pos] = dst[i];
        val[pos] = ev[i];
    }
}

// ------------------------------ tf32 GEMM ----------------------------------
// C[M,BN] = A[M,K] @ B[K,BN] (+bias). Single-pass tf32 m16n8k8, cp.async
// NSTAGE pipeline, convert-on-read. Requires full-N (grid.x covers rows only).

constexpr int tgemm_smem_bytes(int BM, int BN, int NSTAGE) {
    int SA = 32 + 4, SB = BN + 8;
    return NSTAGE * (BM * SA + 32 * SB) * 4;
}

template <int BM, int BN, int WARPS_M, int WARPS_N, int NSTAGE, bool BIAS>
__global__ void __launch_bounds__(32 * WARPS_M * WARPS_N, 2)
tf32_gemm_kernel(int M, int K,
                 const float* __restrict__ A, const float* __restrict__ B,
                 const float* __restrict__ bias, float* __restrict__ C) {
    constexpr int THREADS = 32 * WARPS_M * WARPS_N;
    constexpr int BK = 32;
    constexpr int WM = BM / WARPS_M, WN = BN / WARPS_N;
    constexpr int MT = WM / 16, NT = WN / 8;
    constexpr int SA = BK + 4;
    constexpr int SB = BN + 8;
    constexpr int A_ST = BM * SA, B_ST = BK * SB;
    constexpr int ACH = BM * BK / 4;
    constexpr int BCH = BK * BN / 4;

    extern __shared__ float smemf[];

    const int tid = threadIdx.x;
    const int warp = tid >> 5, lane = tid & 31;
    const int wm = (warp / WARPS_N) * WM;
    const int wn = (warp % WARPS_N) * WN;
    const int g = lane >> 2, t = lane & 3;
    const int row0 = blockIdx.x * BM;
    const int ntiles = (K + BK - 1) / BK;

    float acc[MT][NT][4];
    #pragma unroll
    for (int mi = 0; mi < MT; mi++)
        #pragma unroll
        for (int ni = 0; ni < NT; ni++)
            #pragma unroll
            for (int q = 0; q < 4; q++) acc[mi][ni][q] = 0.f;

    auto issue_tile = [&](int tile) {
        if (tile >= ntiles) return;
        int k0 = tile * BK;
        float* as = smemf + (tile % NSTAGE) * (A_ST + B_ST);
        float* bs = as + A_ST;
        #pragma unroll
        for (int i = tid; i < ACH; i += THREADS) {
            int r = i >> 3, q = i & 7;
            int gm = row0 + r, gk = k0 + q * 4;
            uint32_t dstp = smem_u32(as + r * SA + q * 4);
            const float* srcp = A + (long)gm * K + gk;
            int sz = (gm < M && gk + 4 <= K) ? 16 : 0;
            CP_ASYNC16(dstp, srcp, sz);
        }
        #pragma unroll
        for (int i = tid; i < BCH; i += THREADS) {
            int r = i / (BN / 4), q = i % (BN / 4);
            int gk = k0 + r;
            uint32_t dstp = smem_u32(bs + r * SB + q * 4);
            const float* srcp = B + (long)gk * BN + q * 4;
            int sz = (gk < K) ? 16 : 0;
            CP_ASYNC16(dstp, srcp, sz);
        }
    };

    #pragma unroll
    for (int s = 0; s < NSTAGE - 1; s++) { issue_tile(s); CP_COMMIT(); }

    for (int tt = 0; tt < ntiles; tt++) {
        asm volatile("cp.async.wait_group %0;" :: "n"(NSTAGE - 2) : "memory");
        __syncthreads();
        issue_tile(tt + NSTAGE - 1);
        CP_COMMIT();

        const float* as = smemf + (tt % NSTAGE) * (A_ST + B_ST);
        const float* bs = as + A_ST;

        #pragma unroll
        for (int kk = 0; kk < BK; kk += 8) {
            uint32_t fa[MT][4], fb[NT][2];
            #pragma unroll
            for (int mi = 0; mi < MT; mi++) {
                int r = wm + mi * 16 + g;
                fa[mi][0] = f2tf32(as[r * SA + kk + t]);
                fa[mi][1] = f2tf32(as[(r + 8) * SA + kk + t]);
                fa[mi][2] = f2tf32(as[r * SA + kk + t + 4]);
                fa[mi][3] = f2tf32(as[(r + 8) * SA + kk + t + 4]);
            }
            #pragma unroll
            for (int ni = 0; ni < NT; ni++) {
                int c = wn + ni * 8 + g;
                fb[ni][0] = f2tf32(bs[(kk + t) * SB + c]);
                fb[ni][1] = f2tf32(bs[(kk + t + 4) * SB + c]);
            }
            #pragma unroll
            for (int mi = 0; mi < MT; mi++)
                #pragma unroll
                for (int ni = 0; ni < NT; ni++)
                    MMA_TF32(acc[mi][ni], fa[mi], fb[ni]);
        }
        __syncthreads();
    }

    #pragma unroll
    for (int mi = 0; mi < MT; mi++) {
        int r = row0 + wm + mi * 16 + g;
        #pragma unroll
        for (int ni = 0; ni < NT; ni++) {
            int c = wn + ni * 8 + 2 * t;
            float bx = 0.f, by = 0.f;
            if (BIAS) { bx = bias[c]; by = bias[c + 1]; }
            if (r < M)
                *(float2*)(C + (long)r * BN + c) = make_float2(acc[mi][ni][0] + bx, acc[mi][ni][1] + by);
            if (r + 8 < M)
                *(float2*)(C + (long)(r + 8) * BN + c) = make_float2(acc[mi][ni][2] + bx, acc[mi][ni][3] + by);
        }
    }
}

// ------------------------------ CSR SpMM -----------------------------------

template <bool RELU>
__global__ void spmm128_kernel(const float* __restrict__ support,
                               const int* __restrict__ offsets,
                               const int* __restrict__ col,
                               const float* __restrict__ val,
                               const float* __restrict__ bias,
                               float* __restrict__ out, int n) {
    int warp = (blockIdx.x * blockDim.x + threadIdx.x) >> 5;
    int lane = threadIdx.x & 31;
    if (warp >= n) return;
    int start = offsets[warp], end = offsets[warp + 1];
    const float4* sup4 = (const float4*)support;
    float4 acc = make_float4(0.f, 0.f, 0.f, 0.f);
    int j = start;
    for (; j + 2 <= end; j += 2) {
        int c0 = col[j], c1 = col[j + 1];
        float w0 = val[j], w1 = val[j + 1];
        float4 s0 = sup4[c0 * 32 + lane];
        float4 s1 = sup4[c1 * 32 + lane];
        acc.x += w0 * s0.x + w1 * s1.x;
        acc.y += w0 * s0.y + w1 * s1.y;
        acc.z += w0 * s0.z + w1 * s1.z;
        acc.w += w0 * s0.w + w1 * s1.w;
    }
    if (j < end) {
        int c = col[j]; float w = val[j];
        float4 s = sup4[c * 32 + lane];
        acc.x += w * s.x; acc.y += w * s.y; acc.z += w * s.z; acc.w += w * s.w;
    }
    float4 bb = ((const float4*)bias)[lane];
    acc.x += bb.x; acc.y += bb.y; acc.z += bb.z; acc.w += bb.w;
    if (RELU) {
        acc.x = fmaxf(acc.x, 0.f); acc.y = fmaxf(acc.y, 0.f);
        acc.z = fmaxf(acc.z, 0.f); acc.w = fmaxf(acc.w, 0.f);
    }
    ((float4*)out)[warp * 32 + lane] = acc;
}

template <bool RELU>
__global__ void spmm64_kernel(const float* __restrict__ support,
                              const int* __restrict__ offsets,
                              const int* __restrict__ col,
                              const float* __restrict__ val,
                              const float* __restrict__ bias,
                              float* __restrict__ out, int n) {
    int warp = (blockIdx.x * blockDim.x + threadIdx.x) >> 5;
    int lane = threadIdx.x & 31;
    if (warp >= n) return;
    int start = offsets[warp], end = offsets[warp + 1];
    const float2* sup2 = (const float2*)support;
    float2 acc = make_float2(0.f, 0.f);
    int j = start;
    for (; j + 2 <= end; j += 2) {
        int c0 = col[j], c1 = col[j + 1];
        float w0 = val[j], w1 = val[j + 1];
        float2 s0 = sup2[c0 * 32 + lane];
        float2 s1 = sup2[c1 * 32 + lane];
        acc.x += w0 * s0.x + w1 * s1.x;
        acc.y += w0 * s0.y + w1 * s1.y;
    }
    if (j < end) {
        int c = col[j]; float w = val[j];
        float2 s = sup2[c * 32 + lane];
        acc.x += w * s.x; acc.y += w * s.y;
    }
    float2 bb = ((const float2*)bias)[lane];
    acc.x += bb.x; acc.y += bb.y;
    if (RELU) { acc.x = fmaxf(acc.x, 0.f); acc.y = fmaxf(acc.y, 0.f); }
    ((float2*)out)[warp * 32 + lane] = acc;
}

__global__ void spmm16_lsm_kernel(const float* __restrict__ support,
                                  const int* __restrict__ offsets,
                                  const int* __restrict__ col,
                                  const float* __restrict__ val,
                                  const float* __restrict__ bias,
                                  float* __restrict__ out, int n) {
    int t = blockIdx.x * blockDim.x + threadIdx.x;
    int grp = t >> 4;
    int sub = t & 15;
    bool active = grp < n;
    int g2 = active ? grp : (n - 1);
    int start = offsets[g2], end = offsets[g2 + 1];
    float acc = 0.f;
    for (int j = start; j < end; j++)
        acc += val[j] * support[col[j] * 16 + sub];
    acc += bias[sub];
    float m = acc;
    #pragma unroll
    for (int off = 8; off >= 1; off >>= 1)
        m = fmaxf(m, __shfl_xor_sync(0xffffffffu, m, off, 16));
    float s = expf(acc - m);
    #pragma unroll
    for (int off = 8; off >= 1; off >>= 1)
        s += __shfl_xor_sync(0xffffffffu, s, off, 16);
    if (active) out[grp * 16 + sub] = acc - (logf(s) + m);
}

// ------------------------------ launch -------------------------------------

extern "C" void kernel_launch(void* const* d_in, const int* in_sizes, int n_in,
                              void* d_out, int out_size) {
    const float* x  = (const float*)d_in[0];
    const float* ev = (const float*)d_in[1];
    const float* W1 = (const float*)d_in[2];
    const float* b1 = (const float*)d_in[3];
    const float* W2 = (const float*)d_in[4];
    const float* b2 = (const float*)d_in[5];
    const float* W3 = (const float*)d_in[6];
    const float* b3 = (const float*)d_in[7];
    const float* We = (const float*)d_in[8];
    const float* be = (const float*)d_in[9];
    const int* esrc = (const int*)d_in[10];
    const int* edst = (const int*)d_in[11];

    const int N = NN;
    const int E = in_sizes[10];

    float* out1 = (float*)d_out;
    float* out2 = (float*)d_out + (long)N * 16;

    float *p_support, *p_h1, *p_h2, *p_val;
    int *p_counts, *p_offsets, *p_cursor, *p_col;
    cudaGetSymbolAddress((void**)&p_support, g_support);
    cudaGetSymbolAddress((void**)&p_h1, g_h1);
    cudaGetSymbolAddress((void**)&p_h2, g_h2);
    cudaGetSymbolAddress((void**)&p_counts, g_counts);
    cudaGetSymbolAddress((void**)&p_offsets, g_offsets);
    cudaGetSymbolAddress((void**)&p_cursor, g_cursor);
    cudaGetSymbolAddress((void**)&p_col, g_col);
    cudaGetSymbolAddress((void**)&p_val, g_val);

    // GEMM1: BM=64,BN=128, warps 2x4  | GEMM2/E: BM=64,BN=64, warps 2x4
    // GEMM3: BM=128,BN=16, warps 8x1
    constexpr int S1 = tgemm_smem_bytes(64, 128, 3);   // ~79.9 KB
    constexpr int S2 = tgemm_smem_bytes(64, 64, 3);    // ~55.3 KB
    constexpr int S3 = tgemm_smem_bytes(128, 16, 3);   // ~64.5 KB
    cudaFuncSetAttribute(tf32_gemm_kernel<64, 128, 2, 4, 3, false>,
                         cudaFuncAttributeMaxDynamicSharedMemorySize, S1);
    cudaFuncSetAttribute(tf32_gemm_kernel<64, 64, 2, 4, 3, false>,
                         cudaFuncAttributeMaxDynamicSharedMemorySize, S2);
    cudaFuncSetAttribute(tf32_gemm_kernel<64, 64, 2, 4, 3, true>,
                         cudaFuncAttributeMaxDynamicSharedMemorySize, S2);
    cudaFuncSetAttribute(tf32_gemm_kernel<128, 16, 8, 1, 3, false>,
                         cudaFuncAttributeMaxDynamicSharedMemorySize, S3);

    // ---- CSR build ----
    cudaMemsetAsync(p_counts, 0, (N + 1) * sizeof(int), 0);
    cudaMemsetAsync(p_cursor, 0, N * sizeof(int), 0);
    hist_kernel<<<(E / 4 + 255) / 256, 256>>>((const int4*)esrc, p_counts, E / 4);
    scan_kernel<<<1, 1024>>>(p_counts, p_offsets, N);
    scatter_kernel<<<(E + 255) / 256, 256>>>(esrc, edst, ev, p_offsets, p_cursor, p_col, p_val, E);

    // ---- layer 1: support = x@W1 [N,128]; h1 = relu(agg + b1) ----
    tf32_gemm_kernel<64, 128, 2, 4, 3, false><<<(N + 63) / 64, 256, S1>>>(N, 500, x, W1, nullptr, p_support);
    spmm128_kernel<true><<<(N * 32 + 255) / 256, 256>>>(p_support, p_offsets, p_col, p_val, b1, p_h1, N);

    // ---- layer 2: support = h1@W2 [N,64]; h2 = relu(agg + b2) ----
    tf32_gemm_kernel<64, 64, 2, 4, 3, false><<<(N + 63) / 64, 256, S2>>>(N, 128, p_h1, W2, nullptr, p_support);
    spmm64_kernel<true><<<(N * 32 + 255) / 256, 256>>>(p_support, p_offsets, p_col, p_val, b2, p_h2, N);

    // ---- layer 3: support = h2@W3 [N,16]; out1 = log_softmax(agg + b3) ----
    tf32_gemm_kernel<128, 16, 8, 1, 3, false><<<(N + 127) / 128, 256, S3>>>(N, 64, p_h2, W3, nullptr, p_support);
    spmm16_lsm_kernel<<<(N * 16 + 255) / 256, 256>>>(p_support, p_offsets, p_col, p_val, b3, out1, N);

    // ---- head 2: out2 = h2@We + be ----
    tf32_gemm_kernel<64, 64, 2, 4, 3, true><<<(N + 63) / 64, 256, S2>>>(N, 64, p_h2, We, be, out2);
}